// round 8
// baseline (speedup 1.0000x reference)
#include <cuda_runtime.h>
#include <math.h>
#include <stdint.h>

#define D_MODEL 1024
#define D_FFN   2048
#define N_TOK   4096
#define N_EXP   8
#define MAXSLOT 9216
#define NROWS   (N_TOK + MAXSLOT)   /* 13312 H/Of rows: [0,4096)=shared, rest=slots */
#define NT_SH   (N_TOK / 128)       /* 32 */
#define NT_DN   (MAXSLOT / 128)     /* 72 */

#define STG_B   30720               /* Aq1 10240 + Aq2 10240 + Bq1 5120 + Bq2 5120 */
#define MM_SMEM (3 * STG_B)         /* 92160, 3-stage ring */
#define GU_NSTG 16                  /* K=1024 / 64 */
#define DN_NSTG 32                  /* K=2048 / 64 */

// ---------------- scratch ----------------------------------------------------
__device__ int8_t g_Xq1[(size_t)N_TOK * D_MODEL];
__device__ int8_t g_Xq2[(size_t)N_TOK * D_MODEL];
__device__ float  g_sx[N_TOK];
// gate+up interleaved [slab][4096 n][1024 k]; 64-chunk c: G cols [32c,32c+32) at
// +0..31, U cols at +32..63
__device__ int8_t g_Qgu1[(size_t)9 * 2 * D_FFN * D_MODEL];
__device__ int8_t g_Qgu2[(size_t)9 * 2 * D_FFN * D_MODEL];
__device__ float  g_sgu[9 * 2 * D_FFN];
__device__ int8_t g_Qd1[(size_t)9 * D_MODEL * D_FFN];
__device__ int8_t g_Qd2[(size_t)9 * D_MODEL * D_FFN];
__device__ float  g_sd[9 * D_MODEL];
__device__ float  g_Hf[(size_t)NROWS * D_FFN];
__device__ int8_t g_Hq1[(size_t)NROWS * D_FFN];
__device__ int8_t g_Hq2[(size_t)NROWS * D_FFN];
__device__ float  g_sh[NROWS];
__device__ float  g_Of[(size_t)NROWS * D_MODEL];
__device__ int    g_slot_token[MAXSLOT];
__device__ int    g_counts[N_EXP];
__device__ float  g_psum[N_EXP];
__device__ int    g_fill[N_EXP];
__device__ int    g_padoff[N_EXP + 1];
__device__ int    g_tile_dn[NT_DN];
__device__ int    g_tok_idx[N_TOK * 2];
__device__ int    g_tok_slot[N_TOK * 2];
__device__ float  g_tok_w[N_TOK * 2];

// ---------------- PTX helpers -------------------------------------------------
__device__ __forceinline__ uint32_t s2u(const void* p) {
    return (uint32_t)__cvta_generic_to_shared(p);
}
__device__ __forceinline__ void cpa16(uint32_t dst, const void* src) {
    asm volatile("cp.async.cg.shared.global [%0], [%1], 16;" :: "r"(dst), "l"(src));
}
__device__ __forceinline__ void cp_commit() {
    asm volatile("cp.async.commit_group;");
}
template <int N>
__device__ __forceinline__ void cp_wait() {
    asm volatile("cp.async.wait_group %0;" :: "n"(N));
}
__device__ __forceinline__ void ldm4(uint32_t* r, uint32_t addr) {
    asm volatile("ldmatrix.sync.aligned.m8n8.x4.shared.b16 {%0,%1,%2,%3}, [%4];"
                 : "=r"(r[0]), "=r"(r[1]), "=r"(r[2]), "=r"(r[3]) : "r"(addr));
}
__device__ __forceinline__ void mma_s8(int* c, const uint32_t* a,
                                       uint32_t b0, uint32_t b1) {
    asm volatile("mma.sync.aligned.m16n8k32.row.col.s32.s8.s8.s32 "
                 "{%0,%1,%2,%3}, {%4,%5,%6,%7}, {%8,%9}, {%0,%1,%2,%3};"
                 : "+r"(c[0]), "+r"(c[1]), "+r"(c[2]), "+r"(c[3])
                 : "r"(a[0]), "r"(a[1]), "r"(a[2]), "r"(a[3]), "r"(b0), "r"(b1));
}
__device__ __forceinline__ void quant2(float v, float inv_s, float s,
                                       int8_t& q1, int8_t& q2) {
    int a = __float2int_rn(v * inv_s);
    float r = v - (float)a * s;
    int b = __float2int_rn(r * 128.f * inv_s);
    q1 = (int8_t)a; q2 = (int8_t)b;
}

// ---------------- routing kernels ---------------------------------------------
__global__ void init_kernel() {
    int i = blockIdx.x * blockDim.x + threadIdx.x;
    if (i < MAXSLOT) g_slot_token[i] = -1;
    if (i < N_EXP) { g_counts[i] = 0; g_psum[i] = 0.f; g_fill[i] = 0; }
}

__global__ void router_kernel(const float* __restrict__ x,
                              const float* __restrict__ rw) {
    int t = blockIdx.x * 4 + (threadIdx.x >> 5);
    int lane = threadIdx.x & 31;
    if (t >= N_TOK) return;
    const float* xr = x + (size_t)t * D_MODEL;
    float acc[N_EXP];
#pragma unroll
    for (int e = 0; e < N_EXP; e++) acc[e] = 0.f;
    for (int k = lane; k < D_MODEL; k += 32) {
        float xv = xr[k];
#pragma unroll
        for (int e = 0; e < N_EXP; e++) acc[e] += xv * rw[k * N_EXP + e];
    }
#pragma unroll
    for (int e = 0; e < N_EXP; e++)
#pragma unroll
        for (int o = 16; o; o >>= 1) acc[e] += __shfl_xor_sync(0xffffffffu, acc[e], o);
    if (lane == 0) {
        int i0 = 0; float v0 = acc[0];
#pragma unroll
        for (int e = 1; e < N_EXP; e++) if (acc[e] > v0) { v0 = acc[e]; i0 = e; }
        int i1 = -1; float v1 = -1e30f;
#pragma unroll
        for (int e = 0; e < N_EXP; e++) {
            if (e == i0) continue;
            if (acc[e] > v1) { v1 = acc[e]; i1 = e; }
        }
        float m2 = fmaxf(v0, v1);
        float e0 = expf(v0 - m2), e1 = expf(v1 - m2);
        float inv = 1.f / (e0 + e1);
        g_tok_idx[t * 2 + 0] = i0;  g_tok_w[t * 2 + 0] = e0 * inv;
        g_tok_idx[t * 2 + 1] = i1;  g_tok_w[t * 2 + 1] = e1 * inv;
        atomicAdd(&g_counts[i0], 1);
        atomicAdd(&g_counts[i1], 1);
        float mm = acc[0];
#pragma unroll
        for (int e = 1; e < N_EXP; e++) mm = fmaxf(mm, acc[e]);
        float s = 0.f, ex[N_EXP];
#pragma unroll
        for (int e = 0; e < N_EXP; e++) { ex[e] = expf(acc[e] - mm); s += ex[e]; }
        float invs = 1.f / s;
#pragma unroll
        for (int e = 0; e < N_EXP; e++) atomicAdd(&g_psum[e], ex[e] * invs);
    }
}

__global__ void offsets_kernel(float* __restrict__ out, int out_size) {
    __shared__ int spad[N_EXP + 1];
    int tid = threadIdx.x;
    if (tid == 0) {
        int off = 0;
        for (int e = 0; e < N_EXP; e++) {
            g_padoff[e] = off;
            off += ((g_counts[e] + 127) / 128) * 128;
        }
        g_padoff[N_EXP] = off;
        for (int e = 0; e <= N_EXP; e++) spad[e] = g_padoff[e];
        double s = 0.0;
        for (int e = 0; e < N_EXP; e++) s += (double)g_counts[e] * (double)g_psum[e];
        float aux = (float)((double)N_EXP * s / ((double)N_TOK * (double)N_TOK));
        if (out_size > N_TOK * D_MODEL) out[(size_t)N_TOK * D_MODEL] = aux;
    }
    __syncthreads();
    for (int j = tid; j < NT_DN; j += blockDim.x) {
        int row = j * 128, te = -1;
#pragma unroll
        for (int e = 0; e < N_EXP; e++)
            if (row >= spad[e] && row < spad[e + 1]) te = e;
        g_tile_dn[j] = te;
    }
}

__global__ void scatter_kernel() {
    int t = blockIdx.x * blockDim.x + threadIdx.x;
    if (t >= N_TOK) return;
#pragma unroll
    for (int k = 0; k < 2; k++) {
        int e = g_tok_idx[t * 2 + k];
        int pos = atomicAdd(&g_fill[e], 1);
        int slot = g_padoff[e] + pos;
        g_slot_token[slot] = t;
        g_tok_slot[t * 2 + k] = slot;
    }
}

// ---------------- quantization ------------------------------------------------
__global__ void quant_x_kernel(const float* __restrict__ x) {
    int row = blockIdx.x, tid = threadIdx.x;
    __shared__ float sred[8];
    const float* xr = x + (size_t)row * D_MODEL;
    float v[4]; float m = 0.f;
#pragma unroll
    for (int i = 0; i < 4; i++) { v[i] = xr[tid + i * 256]; m = fmaxf(m, fabsf(v[i])); }
#pragma unroll
    for (int o = 16; o; o >>= 1) m = fmaxf(m, __shfl_xor_sync(0xffffffffu, m, o));
    if ((tid & 31) == 0) sred[tid >> 5] = m;
    __syncthreads();
    if (tid < 32) {
        float t2 = (tid < 8) ? sred[tid] : 0.f;
#pragma unroll
        for (int o = 4; o; o >>= 1) t2 = fmaxf(t2, __shfl_xor_sync(0xffffffffu, t2, o));
        if (tid == 0) sred[0] = t2;
    }
    __syncthreads();
    float s = fmaxf(sred[0], 1e-20f) * (1.f / 127.f);
    float inv = 1.f / s;
    if (tid == 0) g_sx[row] = s;
#pragma unroll
    for (int i = 0; i < 4; i++) {
        int8_t a, b; quant2(v[i], inv, s, a, b);
        g_Xq1[(size_t)row * D_MODEL + tid + i * 256] = a;
        g_Xq2[(size_t)row * D_MODEL + tid + i * 256] = b;
    }
}

__global__ void quant_h_kernel() {
    int row = blockIdx.x, tid = threadIdx.x;
    __shared__ float sred[8];
    const float* hr = g_Hf + (size_t)row * D_FFN;
    float v[8]; float m = 0.f;
#pragma unroll
    for (int i = 0; i < 8; i++) { v[i] = hr[tid + i * 256]; m = fmaxf(m, fabsf(v[i])); }
#pragma unroll
    for (int o = 16; o; o >>= 1) m = fmaxf(m, __shfl_xor_sync(0xffffffffu, m, o));
    if ((tid & 31) == 0) sred[tid >> 5] = m;
    __syncthreads();
    if (tid < 32) {
        float t2 = (tid < 8) ? sred[tid] : 0.f;
#pragma unroll
        for (int o = 4; o; o >>= 1) t2 = fmaxf(t2, __shfl_xor_sync(0xffffffffu, t2, o));
        if (tid == 0) sred[0] = t2;
    }
    __syncthreads();
    float s = fmaxf(sred[0], 1e-20f) * (1.f / 127.f);
    float inv = 1.f / s;
    if (tid == 0) g_sh[row] = s;
#pragma unroll
    for (int i = 0; i < 8; i++) {
        int8_t a, b; quant2(v[i], inv, s, a, b);
        g_Hq1[(size_t)row * D_FFN + tid + i * 256] = a;
        g_Hq2[(size_t)row * D_FFN + tid + i * 256] = b;
    }
}

// per-column max for gate/up -> scale at interleaved index
__global__ void wmax_gu_kernel(const float* __restrict__ Gs, const float* __restrict__ Ge,
                               const float* __restrict__ Us, const float* __restrict__ Ue) {
    int slab = blockIdx.z;
    int isU = blockIdx.y;
    int j = blockIdx.x * 256 + threadIdx.x;
    const float* W = isU
        ? (slab == 0 ? Us : Ue + (size_t)(slab - 1) * D_MODEL * D_FFN)
        : (slab == 0 ? Gs : Ge + (size_t)(slab - 1) * D_MODEL * D_FFN);
    float m = 0.f;
    for (int k = 0; k < D_MODEL; k++) m = fmaxf(m, fabsf(W[(size_t)k * D_FFN + j]));
    int ni = ((j >> 5) << 6) + (isU ? 32 : 0) + (j & 31);
    g_sgu[slab * 2 * D_FFN + ni] = fmaxf(m, 1e-20f) * (1.f / 127.f);
}

__global__ void conv_gu_q_kernel(const float* __restrict__ Gs, const float* __restrict__ Ge,
                                 const float* __restrict__ Us, const float* __restrict__ Ue) {
    int slab = blockIdx.z;
    const float* G = slab ? Ge + (size_t)(slab - 1) * D_MODEL * D_FFN : Gs;
    const float* U = slab ? Ue + (size_t)(slab - 1) * D_MODEL * D_FFN : Us;
    size_t ob = (size_t)slab * 2 * D_FFN * D_MODEL;
    __shared__ float tg[32][33], tu[32][33];
    int tx = threadIdx.x & 31, ty = threadIdx.x >> 5;
    int k0 = blockIdx.y * 32, j0 = blockIdx.x * 32;
#pragma unroll
    for (int p = 0; p < 4; p++) {
        size_t so = (size_t)(k0 + p * 8 + ty) * D_FFN + j0 + tx;
        tg[p * 8 + ty][tx] = G[so];
        tu[p * 8 + ty][tx] = U[so];
    }
    __syncthreads();
    int c = blockIdx.x;
#pragma unroll
    for (int p = 0; p < 4; p++) {
        int jj = p * 8 + ty, k = k0 + tx;
        int niG = c * 64 + jj, niU = c * 64 + 32 + jj;
        float sg = g_sgu[slab * 2 * D_FFN + niG];
        float su = g_sgu[slab * 2 * D_FFN + niU];
        int8_t a, b;
        quant2(tg[tx][jj], 1.f / sg, sg, a, b);
        g_Qgu1[ob + (size_t)niG * D_MODEL + k] = a;
        g_Qgu2[ob + (size_t)niG * D_MODEL + k] = b;
        quant2(tu[tx][jj], 1.f / su, su, a, b);
        g_Qgu1[ob + (size_t)niU * D_MODEL + k] = a;
        g_Qgu2[ob + (size_t)niU * D_MODEL + k] = b;
    }
}

__global__ void wmax_d_kernel(const float* __restrict__ Ds, const float* __restrict__ De) {
    int slab = blockIdx.z;
    int j = blockIdx.x * 256 + threadIdx.x;
    const float* W = slab == 0 ? Ds : De + (size_t)(slab - 1) * D_FFN * D_MODEL;
    float m = 0.f;
    for (int k = 0; k < D_FFN; k++) m = fmaxf(m, fabsf(W[(size_t)k * D_MODEL + j]));
    g_sd[slab * D_MODEL + j] = fmaxf(m, 1e-20f) * (1.f / 127.f);
}

__global__ void conv_wd_q_kernel(const float* __restrict__ Ds, const float* __restrict__ De) {
    int slab = blockIdx.z;
    const float* src = slab == 0 ? Ds : De + (size_t)(slab - 1) * D_FFN * D_MODEL;
    size_t ob = (size_t)slab * D_MODEL * D_FFN;
    __shared__ float t[32][33];
    int tx = threadIdx.x & 31, ty = threadIdx.x >> 5;
    int r0 = blockIdx.y * 32, c0 = blockIdx.x * 32;
#pragma unroll
    for (int p = 0; p < 4; p++)
        t[p * 8 + ty][tx] = src[(size_t)(r0 + p * 8 + ty) * D_MODEL + c0 + tx];
    __syncthreads();
#pragma unroll
    for (int p = 0; p < 4; p++) {
        int n = c0 + p * 8 + ty, k = r0 + tx;
        float s = g_sd[slab * D_MODEL + n];
        int8_t a, b;
        quant2(t[tx][p * 8 + ty], 1.f / s, s, a, b);
        g_Qd1[ob + (size_t)n * D_FFN + k] = a;
        g_Qd2[ob + (size_t)n * D_FFN + k] = b;
    }
}

// ---------------- gate+up IMMA GEMM + SwiGLU ------------------------------------
// Block 128M x 64Ni (=32G+32U), 8 warps 4Mx2N, warp 32x32. K-stage 64, 3-stage ring.
__global__ void __launch_bounds__(256, 2) mma_gateup_kernel() {
    const int by = blockIdx.y;
    const bool sh = (by < NT_SH);
    int te = 0, r0;
    if (sh) r0 = by * 128;
    else {
        int be = by - NT_SH;
        te = g_tile_dn[be];
        if (te < 0) return;
        r0 = be * 128;
    }
    const int slab = sh ? 0 : 1 + te;
    const int n0 = blockIdx.x * 64;          // interleaved B row base
    const int h0 = blockIdx.x * 32;          // real H col base
    const int tid = threadIdx.x, lane = tid & 31, wid = tid >> 5;
    const int wm = wid & 3, wn = wid >> 2;

    extern __shared__ __align__(16) char smem[];
    __shared__ int stok[128];
    __shared__ float ssx[128];
    const uint32_t sbase = s2u(smem);

    if (tid < 128) {
        int t = sh ? (r0 + tid) : g_slot_token[r0 + tid];
        if (t < 0) t = 0;
        stok[tid] = t;
        ssx[tid] = g_sx[t];
    }
    __syncthreads();

    const int8_t* __restrict__ Q1 = g_Qgu1 + (size_t)slab * 2 * D_FFN * D_MODEL;
    const int8_t* __restrict__ Q2 = g_Qgu2 + (size_t)slab * 2 * D_FFN * D_MODEL;

    auto load_stage = [&](int s) {
        const int k0 = s << 6;
        const uint32_t st = sbase + (s % 3) * STG_B;
#pragma unroll
        for (int it = 0; it < 2; it++) {
            int idx = tid + it * 256;
            int row = idx >> 2, ch = idx & 3;
            uint32_t off = row * 80 + ch * 16;
            size_t ao = (size_t)stok[row] * D_MODEL + k0 + ch * 16;
            cpa16(st + off,         g_Xq1 + ao);
            cpa16(st + 10240 + off, g_Xq2 + ao);
        }
        {
            int row = tid >> 2, ch = tid & 3;
            uint32_t off = row * 80 + ch * 16;
            size_t bo = (size_t)(n0 + row) * D_MODEL + k0 + ch * 16;
            cpa16(st + 20480 + off, Q1 + bo);
            cpa16(st + 25600 + off, Q2 + bo);
        }
        cp_commit();
    };

    int mainA[2][4][4] = {}, crossA[2][4][4] = {};

    load_stage(0); load_stage(1);
    for (int s = 0; s < GU_NSTG; s++) {
        cp_wait<1>();
        __syncthreads();
        if (s + 2 < GU_NSTG) load_stage(s + 2); else cp_commit();
        const uint32_t st = sbase + (s % 3) * STG_B;
        const int lr = lane & 15, lc = (lane >> 4) * 16;
#pragma unroll
        for (int kh = 0; kh < 2; kh++) {
            const int kb = kh * 32 + lc;
            uint32_t a1[2][4], a2[2][4];
#pragma unroll
            for (int mi = 0; mi < 2; mi++) {
                uint32_t ro = (wm * 32 + mi * 16 + lr) * 80 + kb;
                ldm4(a1[mi], st + ro);
                ldm4(a2[mi], st + 10240 + ro);
            }
#pragma unroll
            for (int nj = 0; nj < 2; nj++) {
                uint32_t b1[4], b2[4];
                uint32_t ro = (wn * 32 + nj * 16 + lr) * 80 + kb;
                ldm4(b1, st + 20480 + ro);
                ldm4(b2, st + 25600 + ro);
#pragma unroll
                for (int mi = 0; mi < 2; mi++) {
                    mma_s8(mainA[mi][nj * 2],      a1[mi], b1[0], b1[2]);
                    mma_s8(mainA[mi][nj * 2 + 1],  a1[mi], b1[1], b1[3]);
                    mma_s8(crossA[mi][nj * 2],     a1[mi], b2[0], b2[2]);
                    mma_s8(crossA[mi][nj * 2 + 1], a1[mi], b2[1], b2[3]);
                    mma_s8(crossA[mi][nj * 2],     a2[mi], b1[0], b1[2]);
                    mma_s8(crossA[mi][nj * 2 + 1], a2[mi], b1[1], b1[3]);
                }
            }
        }
    }
    __syncthreads();

    // SwiGLU epilogue: wn=0 warps hold G (interleaved cols 0-31), wn=1 hold U.
    float* gbuf = (float*)smem;               // [128][33]
    const float* sw = g_sgu + slab * 2 * D_FFN + n0;
    if (wn == 0) {
#pragma unroll
        for (int mi = 0; mi < 2; mi++)
#pragma unroll
            for (int nj = 0; nj < 4; nj++)
#pragma unroll
                for (int hh = 0; hh < 2; hh++) {
                    int row = wm * 32 + mi * 16 + (lane >> 2) + hh * 8;
                    int col = nj * 8 + 2 * (lane & 3);
                    float sr = ssx[row];
                    float g0 = ((float)mainA[mi][nj][hh * 2] +
                                (float)crossA[mi][nj][hh * 2] * 0.0078125f) * sr * sw[col];
                    float g1 = ((float)mainA[mi][nj][hh * 2 + 1] +
                                (float)crossA[mi][nj][hh * 2 + 1] * 0.0078125f) * sr * sw[col + 1];
                    gbuf[row * 33 + col] = g0;
                    gbuf[row * 33 + col + 1] = g1;
                }
    }
    __syncthreads();
    if (wn == 1) {
        size_t row0 = sh ? (size_t)r0 : (size_t)(N_TOK + r0);
#pragma unroll
        for (int mi = 0; mi < 2; mi++)
#pragma unroll
            for (int nj = 0; nj < 4; nj++)
#pragma unroll
                for (int hh = 0; hh < 2; hh++) {
                    int row = wm * 32 + mi * 16 + (lane >> 2) + hh * 8;
                    int col = nj * 8 + 2 * (lane & 3);
                    float sr = ssx[row];
                    float u0 = ((float)mainA[mi][nj][hh * 2] +
                                (float)crossA[mi][nj][hh * 2] * 0.0078125f) * sr * sw[32 + col];
                    float u1 = ((float)mainA[mi][nj][hh * 2 + 1] +
                                (float)crossA[mi][nj][hh * 2 + 1] * 0.0078125f) * sr * sw[32 + col + 1];
                    float gg0 = gbuf[row * 33 + col], gg1 = gbuf[row * 33 + col + 1];
                    float2 hv;
                    hv.x = gg0 / (1.f + expf(-gg0)) * u0;
                    hv.y = gg1 / (1.f + expf(-gg1)) * u1;
                    *(float2*)(g_Hf + (row0 + row) * D_FFN + h0 + col) = hv;
                }
    }
}

// ---------------- down IMMA GEMM --------------------------------------------------
// Block 128M x 64N, 8 warps 4Mx2N, warp 32x32. K-stage 64, 3-stage ring.
__global__ void __launch_bounds__(256, 2) mma_down_kernel() {
    const int by = blockIdx.y;
    const bool sh = (by < NT_SH);
    int te = 0, r0;
    if (sh) r0 = by * 128;
    else {
        int be = by - NT_SH;
        te = g_tile_dn[be];
        if (te < 0) return;
        r0 = be * 128;
    }
    const int slab = sh ? 0 : 1 + te;
    const int n0 = blockIdx.x * 64;
    const size_t row0 = sh ? (size_t)r0 : (size_t)(N_TOK + r0);
    const int tid = threadIdx.x, lane = tid & 31, wid = tid >> 5;
    const int wm = wid & 3, wn = wid >> 2;

    extern __shared__ __align__(16) char smem[];
    __shared__ float ssh[128];
    const uint32_t sbase = s2u(smem);
    if (tid < 128) ssh[tid] = g_sh[row0 + tid];
    __syncthreads();

    const int8_t* __restrict__ Q1 = g_Qd1 + (size_t)slab * D_MODEL * D_FFN;
    const int8_t* __restrict__ Q2 = g_Qd2 + (size_t)slab * D_MODEL * D_FFN;

    auto load_stage = [&](int s) {
        const int k0 = s << 6;
        const uint32_t st = sbase + (s % 3) * STG_B;
#pragma unroll
        for (int it = 0; it < 2; it++) {
            int idx = tid + it * 256;
            int row = idx >> 2, ch = idx & 3;
            uint32_t off = row * 80 + ch * 16;
            size_t ao = (row0 + row) * D_FFN + k0 + ch * 16;
            cpa16(st + off,         g_Hq1 + ao);
            cpa16(st + 10240 + off, g_Hq2 + ao);
        }
        {
            int row = tid >> 2, ch = tid & 3;
            uint32_t off = row * 80 + ch * 16;
            size_t bo = (size_t)(n0 + row) * D_FFN + k0 + ch * 16;
            cpa16(st + 20480 + off, Q1 + bo);
            cpa16(st + 25600 + off, Q2 + bo);
        }
        cp_commit();
    };

    int mainA[2][4][4] = {}, crossA[2][4][4] = {};

    load_stage(0); load_stage(1);
    for (int s = 0; s < DN_NSTG; s++) {
        cp_wait<1>();
        __syncthreads();
        if (s + 2 < DN_NSTG) load_stage(s + 2); else cp_commit();
        const uint32_t st = sbase + (s % 3) * STG_B;
        const int lr = lane & 15, lc = (lane >> 4) * 16;
#pragma unroll
        for (int kh = 0; kh < 2; kh++) {
            const int kb = kh * 32 + lc;
            uint32_t a1[2][4], a2[2][4];
#pragma unroll
            for (int mi = 0; mi < 2; mi++) {
                uint32_t ro = (wm * 32 + mi * 16 + lr) * 80 + kb;
                ldm4(a1[mi], st + ro);
                ldm4(a2[mi], st + 10240 + ro);
            }
#pragma unroll
            for (int nj = 0; nj < 2; nj++) {
                uint32_t b1[4], b2[4];
                uint32_t ro = (wn * 32 + nj * 16 + lr) * 80 + kb;
                ldm4(b1, st + 20480 + ro);
                ldm4(b2, st + 25600 + ro);
#pragma unroll
                for (int mi = 0; mi < 2; mi++) {
                    mma_s8(mainA[mi][nj * 2],      a1[mi], b1[0], b1[2]);
                    mma_s8(mainA[mi][nj * 2 + 1],  a1[mi], b1[1], b1[3]);
                    mma_s8(crossA[mi][nj * 2],     a1[mi], b2[0], b2[2]);
                    mma_s8(crossA[mi][nj * 2 + 1], a1[mi], b2[1], b2[3]);
                    mma_s8(crossA[mi][nj * 2],     a2[mi], b1[0], b1[2]);
                    mma_s8(crossA[mi][nj * 2 + 1], a2[mi], b1[1], b1[3]);
                }
            }
        }
    }

    const float* sw = g_sd + slab * D_MODEL + n0;
#pragma unroll
    for (int mi = 0; mi < 2; mi++)
#pragma unroll
        for (int nj = 0; nj < 4; nj++)
#pragma unroll
            for (int hh = 0; hh < 2; hh++) {
                int row = wm * 32 + mi * 16 + (lane >> 2) + hh * 8;
                int col = wn * 32 + nj * 8 + 2 * (lane & 3);
                float sr = ssh[row];
                float2 v;
                v.x = ((float)mainA[mi][nj][hh * 2] +
                       (float)crossA[mi][nj][hh * 2] * 0.0078125f) * sr * sw[col];
                v.y = ((float)mainA[mi][nj][hh * 2 + 1] +
                       (float)crossA[mi][nj][hh * 2 + 1] * 0.0078125f) * sr * sw[col + 1];
                *(float2*)(g_Of + (row0 + row) * D_MODEL + n0 + col) = v;
            }
}

// ---------------- combine ----------------------------------------------------------
__global__ void combine_kernel(float* __restrict__ out) {
    int t = blockIdx.x, tid = threadIdx.x;
    int s0 = g_tok_slot[t * 2 + 0], s1 = g_tok_slot[t * 2 + 1];
    float w0 = g_tok_w[t * 2 + 0],  w1 = g_tok_w[t * 2 + 1];
    const float4* a = (const float4*)(g_Of + (size_t)t * D_MODEL) + tid;
    const float4* b = (const float4*)(g_Of + (size_t)(N_TOK + s0) * D_MODEL) + tid;
    const float4* c = (const float4*)(g_Of + (size_t)(N_TOK + s1) * D_MODEL) + tid;
    float4 va = *a, vb = *b, vc = *c;
    float4 r;
    r.x = va.x + w0 * vb.x + w1 * vc.x;
    r.y = va.y + w0 * vb.y + w1 * vc.y;
    r.z = va.z + w0 * vb.z + w1 * vc.z;
    r.w = va.w + w0 * vb.w + w1 * vc.w;
    *((float4*)(out + (size_t)t * D_MODEL) + tid) = r;
}

// ---------------- launch ------------------------------------------------------------
extern "C" void kernel_launch(void* const* d_in, const int* in_sizes, int n_in,
                              void* d_out, int out_size) {
    const float* x         = (const float*)d_in[0];
    const float* shared_wg = (const float*)d_in[1];
    const float* shared_wu = (const float*)d_in[2];
    const float* shared_wd = (const float*)d_in[3];
    const float* exp_wg    = (const float*)d_in[4];
    const float* exp_wu    = (const float*)d_in[5];
    const float* exp_wd    = (const float*)d_in[6];
    const float* router_w  = (const float*)d_in[7];
    float* out = (float*)d_out;

    cudaFuncSetAttribute(mma_gateup_kernel,
                         cudaFuncAttributeMaxDynamicSharedMemorySize, MM_SMEM);
    cudaFuncSetAttribute(mma_down_kernel,
                         cudaFuncAttributeMaxDynamicSharedMemorySize, MM_SMEM);

    init_kernel<<<(MAXSLOT + 255) / 256, 256>>>();
    router_kernel<<<N_TOK / 4, 128>>>(x, router_w);
    offsets_kernel<<<1, 128>>>(out, out_size);
    scatter_kernel<<<N_TOK / 256, 256>>>();

    quant_x_kernel<<<N_TOK, 256>>>(x);
    wmax_gu_kernel<<<dim3(D_FFN / 256, 2, 9), 256>>>(shared_wg, exp_wg, shared_wu, exp_wu);
    conv_gu_q_kernel<<<dim3(D_FFN / 32, D_MODEL / 32, 9), 256>>>(
        shared_wg, exp_wg, shared_wu, exp_wu);
    wmax_d_kernel<<<dim3(D_MODEL / 256, 1, 9), 256>>>(shared_wd, exp_wd);
    conv_wd_q_kernel<<<dim3(D_MODEL / 32, D_FFN / 32, 9), 256>>>(shared_wd, exp_wd);

    mma_gateup_kernel<<<dim3(D_FFN / 32, NT_SH + NT_DN), 256, MM_SMEM>>>();
    quant_h_kernel<<<NROWS, 256>>>();
    mma_down_kernel<<<dim3(D_MODEL / 64, NT_SH + NT_DN), 256, MM_SMEM>>>();
    combine_kernel<<<N_TOK, 256>>>(out);
}

// round 9
// speedup vs baseline: 2.2618x; 2.2618x over previous
#include <cuda_runtime.h>
#include <cuda_bf16.h>
#include <math.h>
#include <stdint.h>

#define D_MODEL 1024
#define D_FFN   2048
#define N_TOK   4096
#define N_EXP   8
#define MAXSLOT 9216
#define NT_SH   (N_TOK / 128)     /* 32 shared row tiles */
#define NT_DN   (MAXSLOT / 128)   /* 72 expert row tiles */

#define TILE_B  10240             /* 128 rows * 80B (padded 64B row) */
#define STG_B   (4 * TILE_B)      /* Ahi, Alo, Bhi, Blo = 40960 */
#define MM_SMEM (2 * STG_B)       /* 81920, 2-stage ring */
#define GU_NSTG 32                /* K=1024 / 32 */
#define DN_NSTG 64                /* K=2048 / 32 */

// ---------------- scratch ----------------------------------------------------
__device__ __nv_bfloat16 g_Xhi[(size_t)N_TOK * D_MODEL];
__device__ __nv_bfloat16 g_Xlo[(size_t)N_TOK * D_MODEL];
// gate+up interleaved: [slab][4096 n][1024 k]; n-chunk c (128 wide) = G cols
// [64c,64c+64) at +0..63, U cols [64c,64c+64) at +64..127
__device__ __nv_bfloat16 g_Bgu_hi[(size_t)9 * 2 * D_FFN * D_MODEL];
__device__ __nv_bfloat16 g_Bgu_lo[(size_t)9 * 2 * D_FFN * D_MODEL];
__device__ __nv_bfloat16 g_Bd_hi[(size_t)9 * D_MODEL * D_FFN];
__device__ __nv_bfloat16 g_Bd_lo[(size_t)9 * D_MODEL * D_FFN];
__device__ __nv_bfloat16 g_Hs_hi[(size_t)N_TOK * D_FFN];
__device__ __nv_bfloat16 g_Hs_lo[(size_t)N_TOK * D_FFN];
__device__ __nv_bfloat16 g_He_hi[(size_t)MAXSLOT * D_FFN];
__device__ __nv_bfloat16 g_He_lo[(size_t)MAXSLOT * D_FFN];
__device__ float g_Os[(size_t)N_TOK * D_MODEL];
__device__ float g_Oe[(size_t)MAXSLOT * D_MODEL];
__device__ int   g_slot_token[MAXSLOT];
__device__ int   g_counts[N_EXP];
__device__ float g_psum[N_EXP];
__device__ int   g_fill[N_EXP];
__device__ int   g_padoff[N_EXP + 1];
__device__ int   g_tile_dn[NT_DN];
__device__ int   g_tok_idx[N_TOK * 2];
__device__ int   g_tok_slot[N_TOK * 2];
__device__ float g_tok_w[N_TOK * 2];

// ---------------- PTX helpers -------------------------------------------------
__device__ __forceinline__ uint32_t s2u(const void* p) {
    return (uint32_t)__cvta_generic_to_shared(p);
}
__device__ __forceinline__ void cpa16(uint32_t dst, const void* src) {
    asm volatile("cp.async.cg.shared.global [%0], [%1], 16;" :: "r"(dst), "l"(src));
}
__device__ __forceinline__ void cp_commit() {
    asm volatile("cp.async.commit_group;");
}
template <int N>
__device__ __forceinline__ void cp_wait() {
    asm volatile("cp.async.wait_group %0;" :: "n"(N));
}
__device__ __forceinline__ void ldm4(uint32_t* r, uint32_t addr) {
    asm volatile("ldmatrix.sync.aligned.m8n8.x4.shared.b16 {%0,%1,%2,%3}, [%4];"
                 : "=r"(r[0]), "=r"(r[1]), "=r"(r[2]), "=r"(r[3]) : "r"(addr));
}
__device__ __forceinline__ void mma_bf16(float* c, const uint32_t* a,
                                         uint32_t b0, uint32_t b1) {
    asm volatile("mma.sync.aligned.m16n8k16.row.col.f32.bf16.bf16.f32 "
                 "{%0,%1,%2,%3}, {%4,%5,%6,%7}, {%8,%9}, {%0,%1,%2,%3};"
                 : "+f"(c[0]), "+f"(c[1]), "+f"(c[2]), "+f"(c[3])
                 : "r"(a[0]), "r"(a[1]), "r"(a[2]), "r"(a[3]), "r"(b0), "r"(b1));
}

// ---------------- routing kernels ---------------------------------------------
__global__ void init_kernel() {
    int i = blockIdx.x * blockDim.x + threadIdx.x;
    if (i < MAXSLOT) g_slot_token[i] = -1;
    if (i < N_EXP) { g_counts[i] = 0; g_psum[i] = 0.f; g_fill[i] = 0; }
}

__global__ void router_kernel(const float* __restrict__ x,
                              const float* __restrict__ rw) {
    int t = blockIdx.x * 4 + (threadIdx.x >> 5);
    int lane = threadIdx.x & 31;
    if (t >= N_TOK) return;
    const float* xr = x + (size_t)t * D_MODEL;
    float acc[N_EXP];
#pragma unroll
    for (int e = 0; e < N_EXP; e++) acc[e] = 0.f;
    for (int k = lane; k < D_MODEL; k += 32) {
        float xv = xr[k];
#pragma unroll
        for (int e = 0; e < N_EXP; e++) acc[e] += xv * rw[k * N_EXP + e];
    }
#pragma unroll
    for (int e = 0; e < N_EXP; e++)
#pragma unroll
        for (int o = 16; o; o >>= 1) acc[e] += __shfl_xor_sync(0xffffffffu, acc[e], o);
    if (lane == 0) {
        int i0 = 0; float v0 = acc[0];
#pragma unroll
        for (int e = 1; e < N_EXP; e++) if (acc[e] > v0) { v0 = acc[e]; i0 = e; }
        int i1 = -1; float v1 = -1e30f;
#pragma unroll
        for (int e = 0; e < N_EXP; e++) {
            if (e == i0) continue;
            if (acc[e] > v1) { v1 = acc[e]; i1 = e; }
        }
        float m2 = fmaxf(v0, v1);
        float e0 = expf(v0 - m2), e1 = expf(v1 - m2);
        float inv = 1.f / (e0 + e1);
        g_tok_idx[t * 2 + 0] = i0;  g_tok_w[t * 2 + 0] = e0 * inv;
        g_tok_idx[t * 2 + 1] = i1;  g_tok_w[t * 2 + 1] = e1 * inv;
        atomicAdd(&g_counts[i0], 1);
        atomicAdd(&g_counts[i1], 1);
        float mm = acc[0];
#pragma unroll
        for (int e = 1; e < N_EXP; e++) mm = fmaxf(mm, acc[e]);
        float s = 0.f, ex[N_EXP];
#pragma unroll
        for (int e = 0; e < N_EXP; e++) { ex[e] = expf(acc[e] - mm); s += ex[e]; }
        float invs = 1.f / s;
#pragma unroll
        for (int e = 0; e < N_EXP; e++) atomicAdd(&g_psum[e], ex[e] * invs);
    }
}

__global__ void offsets_kernel(float* __restrict__ out, int out_size) {
    __shared__ int spad[N_EXP + 1];
    int tid = threadIdx.x;
    if (tid == 0) {
        int off = 0;
        for (int e = 0; e < N_EXP; e++) {
            g_padoff[e] = off;
            off += ((g_counts[e] + 127) / 128) * 128;
        }
        g_padoff[N_EXP] = off;
        for (int e = 0; e <= N_EXP; e++) spad[e] = g_padoff[e];
        double s = 0.0;
        for (int e = 0; e < N_EXP; e++) s += (double)g_counts[e] * (double)g_psum[e];
        float aux = (float)((double)N_EXP * s / ((double)N_TOK * (double)N_TOK));
        if (out_size > N_TOK * D_MODEL) out[(size_t)N_TOK * D_MODEL] = aux;
    }
    __syncthreads();
    for (int j = tid; j < NT_DN; j += blockDim.x) {
        int row = j * 128, te = -1;
#pragma unroll
        for (int e = 0; e < N_EXP; e++)
            if (row >= spad[e] && row < spad[e + 1]) te = e;
        g_tile_dn[j] = te;
    }
}

__global__ void scatter_kernel() {
    int t = blockIdx.x * blockDim.x + threadIdx.x;
    if (t >= N_TOK) return;
#pragma unroll
    for (int k = 0; k < 2; k++) {
        int e = g_tok_idx[t * 2 + k];
        int pos = atomicAdd(&g_fill[e], 1);
        int slot = g_padoff[e] + pos;
        g_slot_token[slot] = t;
        g_tok_slot[t * 2 + k] = slot;
    }
}

// ---------------- conversions --------------------------------------------------
__global__ void conv_x_kernel(const float* __restrict__ x) {
    int i = blockIdx.x * 256 + threadIdx.x;
    float v = x[i];
    __nv_bfloat16 h = __float2bfloat16(v);
    g_Xhi[i] = h;
    g_Xlo[i] = __float2bfloat16(v - __bfloat162float(h));
}

// gate+up -> interleaved [slab][4096 n][1024 k] bf16 hi/lo
__global__ void conv_gu_kernel(const float* __restrict__ srcGs, const float* __restrict__ srcGe,
                               const float* __restrict__ srcUs, const float* __restrict__ srcUe,
                               __nv_bfloat16* __restrict__ hiO, __nv_bfloat16* __restrict__ loO) {
    int slab = blockIdx.z;
    const float* G = (slab == 0) ? srcGs : srcGe + (size_t)(slab - 1) * D_MODEL * D_FFN;
    const float* U = (slab == 0) ? srcUs : srcUe + (size_t)(slab - 1) * D_MODEL * D_FFN;
    size_t ob = (size_t)slab * 2 * D_FFN * D_MODEL;
    __shared__ float tg[32][33], tu[32][33];
    int tx = threadIdx.x & 31, ty = threadIdx.x >> 5;
    int k0 = blockIdx.y * 32, j0 = blockIdx.x * 32;
#pragma unroll
    for (int p = 0; p < 4; p++) {
        size_t so = (size_t)(k0 + p * 8 + ty) * D_FFN + j0 + tx;
        tg[p * 8 + ty][tx] = G[so];
        tu[p * 8 + ty][tx] = U[so];
    }
    __syncthreads();
    int nG0 = ((j0 >> 6) << 7) + (j0 & 63);
#pragma unroll
    for (int p = 0; p < 4; p++) {
        int jj = p * 8 + ty, k = k0 + tx;
        float vg = tg[tx][jj], vu = tu[tx][jj];
        __nv_bfloat16 gh = __float2bfloat16(vg);
        __nv_bfloat16 uh = __float2bfloat16(vu);
        size_t og = ob + (size_t)(nG0 + jj) * D_MODEL + k;
        size_t ou = ob + (size_t)(nG0 + 64 + jj) * D_MODEL + k;
        hiO[og] = gh; loO[og] = __float2bfloat16(vg - __bfloat162float(gh));
        hiO[ou] = uh; loO[ou] = __float2bfloat16(vu - __bfloat162float(uh));
    }
}

// down: transpose [R,C] fp32 -> [slab][C][R] bf16 hi/lo
__global__ void conv_w_kernel(const float* __restrict__ srcS, const float* __restrict__ srcE,
                              __nv_bfloat16* __restrict__ hiO, __nv_bfloat16* __restrict__ loO,
                              int R, int C) {
    int slab = blockIdx.z;
    const float* src = (slab == 0) ? srcS : srcE + (size_t)(slab - 1) * R * C;
    size_t ob = (size_t)slab * R * C;
    __shared__ float t[32][33];
    int tx = threadIdx.x & 31, ty = threadIdx.x >> 5;
    int r0 = blockIdx.y * 32, c0 = blockIdx.x * 32;
#pragma unroll
    for (int p = 0; p < 4; p++)
        t[p * 8 + ty][tx] = src[(size_t)(r0 + p * 8 + ty) * C + c0 + tx];
    __syncthreads();
#pragma unroll
    for (int p = 0; p < 4; p++) {
        int n = c0 + p * 8 + ty, k = r0 + tx;
        float v = t[tx][p * 8 + ty];
        __nv_bfloat16 h = __float2bfloat16(v);
        hiO[ob + (size_t)n * R + k] = h;
        loO[ob + (size_t)n * R + k] = __float2bfloat16(v - __bfloat162float(h));
    }
}

// ---------------- gate+up GEMM: 128M x 128N(=64G+64U), 3-term per K sweep ------
// Single __syncthreads per K-stage: cp_wait -> sync -> issue next load -> compute.
__global__ void __launch_bounds__(256, 2) mma_gateup_kernel() {
    const int by = blockIdx.y;
    const bool sh = (by < NT_SH);
    int te = 0, r0;
    if (sh) r0 = by * 128;
    else {
        int be = by - NT_SH;
        te = g_tile_dn[be];
        if (te < 0) return;
        r0 = be * 128;
    }
    const int slab = sh ? 0 : 1 + te;
    const int n0b = blockIdx.x * 128;        // interleaved B row base
    const int h0 = blockIdx.x * 64;          // H column base
    const int tid = threadIdx.x, lane = tid & 31, wid = tid >> 5;
    const int wm = wid & 3, wn = wid >> 2;

    extern __shared__ __align__(16) char smem[];
    __shared__ int stok[128];
    const uint32_t sbase = s2u(smem);

    if (tid < 128) {
        if (sh) stok[tid] = r0 + tid;
        else { int t = g_slot_token[r0 + tid]; stok[tid] = t < 0 ? 0 : t; }
    }
    __syncthreads();

    const __nv_bfloat16* __restrict__ Bh = g_Bgu_hi + (size_t)slab * 2 * D_FFN * D_MODEL;
    const __nv_bfloat16* __restrict__ Bl = g_Bgu_lo + (size_t)slab * 2 * D_FFN * D_MODEL;

    auto load_stage = [&](int s) {
        const int k0 = s << 5;
        const uint32_t st = sbase + (s & 1) * STG_B;
#pragma unroll
        for (int it = 0; it < 2; it++) {
            int idx = tid + it * 256;
            int row = idx >> 2, ch = idx & 3;
            uint32_t off = row * 80 + ch * 16;
            size_t ao = (size_t)stok[row] * D_MODEL + k0 + ch * 8;
            size_t bo = (size_t)(n0b + row) * D_MODEL + k0 + ch * 8;
            cpa16(st + off,              g_Xhi + ao);
            cpa16(st + TILE_B + off,     g_Xlo + ao);
            cpa16(st + 2 * TILE_B + off, Bh + bo);
            cpa16(st + 3 * TILE_B + off, Bl + bo);
        }
        cp_commit();
    };

    float acc[2][8][4];
#pragma unroll
    for (int i = 0; i < 2; i++)
#pragma unroll
        for (int j = 0; j < 8; j++)
#pragma unroll
            for (int q = 0; q < 4; q++) acc[i][j][q] = 0.f;

    load_stage(0);
    for (int s = 0; s < GU_NSTG; s++) {
        cp_wait<0>();
        __syncthreads();
        if (s + 1 < GU_NSTG) load_stage(s + 1);
        const uint32_t st = sbase + (s & 1) * STG_B;
        const int lr = lane & 15, lc = (lane >> 4) * 16;
#pragma unroll
        for (int kh = 0; kh < 2; kh++) {
            const int kb = kh * 32 + lc;
            uint32_t ahi[2][4], alo[2][4];
#pragma unroll
            for (int mi = 0; mi < 2; mi++) {
                uint32_t ro = (wm * 32 + mi * 16 + lr) * 80 + kb;
                ldm4(ahi[mi], st + ro);
                ldm4(alo[mi], st + TILE_B + ro);
            }
#pragma unroll
            for (int nj = 0; nj < 4; nj++) {
                uint32_t bh[4], bl[4];
                uint32_t ro = (wn * 64 + nj * 16 + lr) * 80 + kb;
                ldm4(bh, st + 2 * TILE_B + ro);
                ldm4(bl, st + 3 * TILE_B + ro);
#pragma unroll
                for (int mi = 0; mi < 2; mi++) {
                    mma_bf16(acc[mi][nj * 2],     ahi[mi], bh[0], bh[2]);
                    mma_bf16(acc[mi][nj * 2 + 1], ahi[mi], bh[1], bh[3]);
                    mma_bf16(acc[mi][nj * 2],     ahi[mi], bl[0], bl[2]);
                    mma_bf16(acc[mi][nj * 2 + 1], ahi[mi], bl[1], bl[3]);
                    mma_bf16(acc[mi][nj * 2],     alo[mi], bh[0], bh[2]);
                    mma_bf16(acc[mi][nj * 2 + 1], alo[mi], bh[1], bh[3]);
                }
            }
        }
    }

    // SwiGLU epilogue: G warps (wn=0) hand accumulators to U warps (wn=1) via smem.
    // gbuf sits in ring slot 0 (stage GU_NSTG-2 data, already consumed by all warps
    // before the final top-of-loop sync); last stage computed from slot 1.
    __syncthreads();
    float* gbuf = (float*)smem;
    if (wn == 0) {
#pragma unroll
        for (int mi = 0; mi < 2; mi++)
#pragma unroll
            for (int ni = 0; ni < 8; ni++)
#pragma unroll
                for (int hh = 0; hh < 2; hh++) {
                    int row = wm * 32 + mi * 16 + (lane >> 2) + hh * 8;
                    int col = ni * 8 + 2 * (lane & 3);
                    float2 v; v.x = acc[mi][ni][hh * 2]; v.y = acc[mi][ni][hh * 2 + 1];
                    *(float2*)(gbuf + row * 66 + col) = v;
                }
    }
    __syncthreads();
    if (wn == 1) {
        __nv_bfloat16* __restrict__ Hhi = sh ? g_Hs_hi : g_He_hi;
        __nv_bfloat16* __restrict__ Hlo = sh ? g_Hs_lo : g_He_lo;
#pragma unroll
        for (int mi = 0; mi < 2; mi++)
#pragma unroll
            for (int ni = 0; ni < 8; ni++)
#pragma unroll
                for (int hh = 0; hh < 2; hh++) {
                    int row = wm * 32 + mi * 16 + (lane >> 2) + hh * 8;
                    int col = ni * 8 + 2 * (lane & 3);
                    float2 g2 = *(const float2*)(gbuf + row * 66 + col);
                    float u0 = acc[mi][ni][hh * 2], u1 = acc[mi][ni][hh * 2 + 1];
                    float h0v = g2.x / (1.f + expf(-g2.x)) * u0;
                    float h1v = g2.y / (1.f + expf(-g2.y)) * u1;
                    __nv_bfloat16 h0h = __float2bfloat16(h0v);
                    __nv_bfloat16 h1h = __float2bfloat16(h1v);
                    __nv_bfloat162 hv; hv.x = h0h; hv.y = h1h;
                    __nv_bfloat162 lv;
                    lv.x = __float2bfloat16(h0v - __bfloat162float(h0h));
                    lv.y = __float2bfloat16(h1v - __bfloat162float(h1h));
                    size_t o = (size_t)(r0 + row) * D_FFN + h0 + col;
                    *(__nv_bfloat162*)(Hhi + o) = hv;
                    *(__nv_bfloat162*)(Hlo + o) = lv;
                }
    }
}

// ---------------- down GEMM: 128M x 128N, 3-term per K sweep --------------------
__global__ void __launch_bounds__(256, 2) mma_down_kernel() {
    const int by = blockIdx.y;
    const bool sh = (by < NT_SH);
    int te = 0, r0;
    if (sh) r0 = by * 128;
    else {
        int be = by - NT_SH;
        te = g_tile_dn[be];
        if (te < 0) return;
        r0 = be * 128;
    }
    const int slab = sh ? 0 : 1 + te;
    const int n0 = blockIdx.x * 128;
    const int tid = threadIdx.x, lane = tid & 31, wid = tid >> 5;
    const int wm = wid & 3, wn = wid >> 2;

    extern __shared__ __align__(16) char smem[];
    const uint32_t sbase = s2u(smem);

    const __nv_bfloat16* __restrict__ Ah = sh ? g_Hs_hi : g_He_hi;
    const __nv_bfloat16* __restrict__ Al = sh ? g_Hs_lo : g_He_lo;
    const __nv_bfloat16* __restrict__ Bh = g_Bd_hi + (size_t)slab * D_MODEL * D_FFN;
    const __nv_bfloat16* __restrict__ Bl = g_Bd_lo + (size_t)slab * D_MODEL * D_FFN;

    auto load_stage = [&](int s) {
        const int k0 = s << 5;
        const uint32_t st = sbase + (s & 1) * STG_B;
#pragma unroll
        for (int it = 0; it < 2; it++) {
            int idx = tid + it * 256;
            int row = idx >> 2, ch = idx & 3;
            uint32_t off = row * 80 + ch * 16;
            size_t ao = (size_t)(r0 + row) * D_FFN + k0 + ch * 8;
            size_t bo = (size_t)(n0 + row) * D_FFN + k0 + ch * 8;
            cpa16(st + off,              Ah + ao);
            cpa16(st + TILE_B + off,     Al + ao);
            cpa16(st + 2 * TILE_B + off, Bh + bo);
            cpa16(st + 3 * TILE_B + off, Bl + bo);
        }
        cp_commit();
    };

    float acc[2][8][4];
#pragma unroll
    for (int i = 0; i < 2; i++)
#pragma unroll
        for (int j = 0; j < 8; j++)
#pragma unroll
            for (int q = 0; q < 4; q++) acc[i][j][q] = 0.f;

    load_stage(0);
    for (int s = 0; s < DN_NSTG; s++) {
        cp_wait<0>();
        __syncthreads();
        if (s + 1 < DN_NSTG) load_stage(s + 1);
        const uint32_t st = sbase + (s & 1) * STG_B;
        const int lr = lane & 15, lc = (lane >> 4) * 16;
#pragma unroll
        for (int kh = 0; kh < 2; kh++) {
            const int kb = kh * 32 + lc;
            uint32_t ahi[2][4], alo[2][4];
#pragma unroll
            for (int mi = 0; mi < 2; mi++) {
                uint32_t ro = (wm * 32 + mi * 16 + lr) * 80 + kb;
                ldm4(ahi[mi], st + ro);
                ldm4(alo[mi], st + TILE_B + ro);
            }
#pragma unroll
            for (int nj = 0; nj < 4; nj++) {
                uint32_t bh[4], bl[4];
                uint32_t ro = (wn * 64 + nj * 16 + lr) * 80 + kb;
                ldm4(bh, st + 2 * TILE_B + ro);
                ldm4(bl, st + 3 * TILE_B + ro);
#pragma unroll
                for (int mi = 0; mi < 2; mi++) {
                    mma_bf16(acc[mi][nj * 2],     ahi[mi], bh[0], bh[2]);
                    mma_bf16(acc[mi][nj * 2 + 1], ahi[mi], bh[1], bh[3]);
                    mma_bf16(acc[mi][nj * 2],     ahi[mi], bl[0], bl[2]);
                    mma_bf16(acc[mi][nj * 2 + 1], ahi[mi], bl[1], bl[3]);
                    mma_bf16(acc[mi][nj * 2],     alo[mi], bh[0], bh[2]);
                    mma_bf16(acc[mi][nj * 2 + 1], alo[mi], bh[1], bh[3]);
                }
            }
        }
    }

    float* __restrict__ O = sh ? g_Os : g_Oe;
#pragma unroll
    for (int mi = 0; mi < 2; mi++)
#pragma unroll
        for (int ni = 0; ni < 8; ni++)
#pragma unroll
            for (int hh = 0; hh < 2; hh++) {
                int row = wm * 32 + mi * 16 + (lane >> 2) + hh * 8;
                int col = n0 + wn * 64 + ni * 8 + 2 * (lane & 3);
                float2 v; v.x = acc[mi][ni][hh * 2]; v.y = acc[mi][ni][hh * 2 + 1];
                *(float2*)(O + (size_t)(r0 + row) * D_MODEL + col) = v;
            }
}

// ---------------- combine: out = Os + w0*Oe[s0] + w1*Oe[s1] -----------------------
__global__ void combine_kernel(float* __restrict__ out) {
    int t = blockIdx.x;
    int tid = threadIdx.x;
    int s0 = g_tok_slot[t * 2 + 0], s1 = g_tok_slot[t * 2 + 1];
    float w0 = g_tok_w[t * 2 + 0],  w1 = g_tok_w[t * 2 + 1];
    const float4* a = (const float4*)(g_Os + (size_t)t * D_MODEL) + tid;
    const float4* b = (const float4*)(g_Oe + (size_t)s0 * D_MODEL) + tid;
    const float4* c = (const float4*)(g_Oe + (size_t)s1 * D_MODEL) + tid;
    float4 va = *a, vb = *b, vc = *c;
    float4 r;
    r.x = va.x + w0 * vb.x + w1 * vc.x;
    r.y = va.y + w0 * vb.y + w1 * vc.y;
    r.z = va.z + w0 * vb.z + w1 * vc.z;
    r.w = va.w + w0 * vb.w + w1 * vc.w;
    *((float4*)(out + (size_t)t * D_MODEL) + tid) = r;
}

// ---------------- launch ------------------------------------------------------------
extern "C" void kernel_launch(void* const* d_in, const int* in_sizes, int n_in,
                              void* d_out, int out_size) {
    const float* x         = (const float*)d_in[0];
    const float* shared_wg = (const float*)d_in[1];
    const float* shared_wu = (const float*)d_in[2];
    const float* shared_wd = (const float*)d_in[3];
    const float* exp_wg    = (const float*)d_in[4];
    const float* exp_wu    = (const float*)d_in[5];
    const float* exp_wd    = (const float*)d_in[6];
    const float* router_w  = (const float*)d_in[7];
    float* out = (float*)d_out;

    __nv_bfloat16 *bgu_hi, *bgu_lo, *bd_hi, *bd_lo;
    cudaGetSymbolAddress((void**)&bgu_hi, g_Bgu_hi);
    cudaGetSymbolAddress((void**)&bgu_lo, g_Bgu_lo);
    cudaGetSymbolAddress((void**)&bd_hi, g_Bd_hi);
    cudaGetSymbolAddress((void**)&bd_lo, g_Bd_lo);

    cudaFuncSetAttribute(mma_gateup_kernel,
                         cudaFuncAttributeMaxDynamicSharedMemorySize, MM_SMEM);
    cudaFuncSetAttribute(mma_down_kernel,
                         cudaFuncAttributeMaxDynamicSharedMemorySize, MM_SMEM);

    init_kernel<<<(MAXSLOT + 255) / 256, 256>>>();
    router_kernel<<<N_TOK / 4, 128>>>(x, router_w);
    offsets_kernel<<<1, 128>>>(out, out_size);
    scatter_kernel<<<N_TOK / 256, 256>>>();

    conv_x_kernel<<<(N_TOK * D_MODEL) / 256, 256>>>(x);
    conv_gu_kernel<<<dim3(D_FFN / 32, D_MODEL / 32, 9), 256>>>(
        shared_wg, exp_wg, shared_wu, exp_wu, bgu_hi, bgu_lo);
    conv_w_kernel<<<dim3(D_MODEL / 32, D_FFN / 32, 9), 256>>>(
        shared_wd, exp_wd, bd_hi, bd_lo, D_FFN, D_MODEL);

    mma_gateup_kernel<<<dim3(D_FFN / 64, NT_SH + NT_DN), 256, MM_SMEM>>>();
    mma_down_kernel<<<dim3(D_MODEL / 128, NT_SH + NT_DN), 256, MM_SMEM>>>();
    combine_kernel<<<N_TOK, 256>>>(out);
}

// round 10
// speedup vs baseline: 2.7830x; 1.2304x over previous
#include <cuda_runtime.h>
#include <cuda_fp16.h>
#include <math.h>
#include <stdint.h>

#define D_MODEL 1024
#define D_FFN   2048
#define N_TOK   4096
#define N_EXP   8
#define MAXSLOT 9216
#define NT_SH   (N_TOK / 128)     /* 32 shared row tiles */
#define NT_DN   (MAXSLOT / 128)   /* 72 expert row tiles */

#define TILE_B  10240             /* 128 rows * 80B (padded 64B row) */
#define STG_B   (3 * TILE_B)      /* A, Bhi, Blo = 30720 */
#define MM_SMEM (2 * STG_B)       /* 61440, 2-stage ring */
#define GU_NSTG 32                /* K=1024 / 32 */
#define DN_NSTG 64                /* K=2048 / 32 */

// ---------------- scratch ----------------------------------------------------
__device__ __half g_Xh[(size_t)N_TOK * D_MODEL];
// gate+up interleaved: [slab][4096 n][1024 k]; n-chunk c (128 wide) = G cols
// [64c,64c+64) at +0..63, U cols [64c,64c+64) at +64..127
__device__ __half g_Bgu_hi[(size_t)9 * 2 * D_FFN * D_MODEL];
__device__ __half g_Bgu_lo[(size_t)9 * 2 * D_FFN * D_MODEL];
__device__ __half g_Bd_hi[(size_t)9 * D_MODEL * D_FFN];
__device__ __half g_Bd_lo[(size_t)9 * D_MODEL * D_FFN];
__device__ __half g_Hs[(size_t)N_TOK * D_FFN];
__device__ __half g_He[(size_t)MAXSLOT * D_FFN];
__device__ float g_Os[(size_t)N_TOK * D_MODEL];
__device__ float g_Oe[(size_t)MAXSLOT * D_MODEL];
__device__ int   g_slot_token[MAXSLOT];
__device__ int   g_counts[N_EXP];
__device__ float g_psum[N_EXP];
__device__ int   g_fill[N_EXP];
__device__ int   g_padoff[N_EXP + 1];
__device__ int   g_tile_dn[NT_DN];
__device__ int   g_tok_idx[N_TOK * 2];
__device__ int   g_tok_slot[N_TOK * 2];
__device__ float g_tok_w[N_TOK * 2];

// ---------------- PTX helpers -------------------------------------------------
__device__ __forceinline__ uint32_t s2u(const void* p) {
    return (uint32_t)__cvta_generic_to_shared(p);
}
__device__ __forceinline__ void cpa16(uint32_t dst, const void* src) {
    asm volatile("cp.async.cg.shared.global [%0], [%1], 16;" :: "r"(dst), "l"(src));
}
__device__ __forceinline__ void cp_commit() {
    asm volatile("cp.async.commit_group;");
}
template <int N>
__device__ __forceinline__ void cp_wait() {
    asm volatile("cp.async.wait_group %0;" :: "n"(N));
}
__device__ __forceinline__ void ldm4(uint32_t* r, uint32_t addr) {
    asm volatile("ldmatrix.sync.aligned.m8n8.x4.shared.b16 {%0,%1,%2,%3}, [%4];"
                 : "=r"(r[0]), "=r"(r[1]), "=r"(r[2]), "=r"(r[3]) : "r"(addr));
}
__device__ __forceinline__ void mma_f16(float* c, const uint32_t* a,
                                        uint32_t b0, uint32_t b1) {
    asm volatile("mma.sync.aligned.m16n8k16.row.col.f32.f16.f16.f32 "
                 "{%0,%1,%2,%3}, {%4,%5,%6,%7}, {%8,%9}, {%0,%1,%2,%3};"
                 : "+f"(c[0]), "+f"(c[1]), "+f"(c[2]), "+f"(c[3])
                 : "r"(a[0]), "r"(a[1]), "r"(a[2]), "r"(a[3]), "r"(b0), "r"(b1));
}

// ---------------- routing kernels ---------------------------------------------
__global__ void init_kernel() {
    int i = blockIdx.x * blockDim.x + threadIdx.x;
    if (i < MAXSLOT) g_slot_token[i] = -1;
    if (i < N_EXP) { g_counts[i] = 0; g_psum[i] = 0.f; g_fill[i] = 0; }
}

__global__ void router_kernel(const float* __restrict__ x,
                              const float* __restrict__ rw) {
    int t = blockIdx.x * 4 + (threadIdx.x >> 5);
    int lane = threadIdx.x & 31;
    if (t >= N_TOK) return;
    const float* xr = x + (size_t)t * D_MODEL;
    float acc[N_EXP];
#pragma unroll
    for (int e = 0; e < N_EXP; e++) acc[e] = 0.f;
    for (int k = lane; k < D_MODEL; k += 32) {
        float xv = xr[k];
#pragma unroll
        for (int e = 0; e < N_EXP; e++) acc[e] += xv * rw[k * N_EXP + e];
    }
#pragma unroll
    for (int e = 0; e < N_EXP; e++)
#pragma unroll
        for (int o = 16; o; o >>= 1) acc[e] += __shfl_xor_sync(0xffffffffu, acc[e], o);
    if (lane == 0) {
        int i0 = 0; float v0 = acc[0];
#pragma unroll
        for (int e = 1; e < N_EXP; e++) if (acc[e] > v0) { v0 = acc[e]; i0 = e; }
        int i1 = -1; float v1 = -1e30f;
#pragma unroll
        for (int e = 0; e < N_EXP; e++) {
            if (e == i0) continue;
            if (acc[e] > v1) { v1 = acc[e]; i1 = e; }
        }
        float m2 = fmaxf(v0, v1);
        float e0 = expf(v0 - m2), e1 = expf(v1 - m2);
        float inv = 1.f / (e0 + e1);
        g_tok_idx[t * 2 + 0] = i0;  g_tok_w[t * 2 + 0] = e0 * inv;
        g_tok_idx[t * 2 + 1] = i1;  g_tok_w[t * 2 + 1] = e1 * inv;
        atomicAdd(&g_counts[i0], 1);
        atomicAdd(&g_counts[i1], 1);
        float mm = acc[0];
#pragma unroll
        for (int e = 1; e < N_EXP; e++) mm = fmaxf(mm, acc[e]);
        float s = 0.f, ex[N_EXP];
#pragma unroll
        for (int e = 0; e < N_EXP; e++) { ex[e] = expf(acc[e] - mm); s += ex[e]; }
        float invs = 1.f / s;
#pragma unroll
        for (int e = 0; e < N_EXP; e++) atomicAdd(&g_psum[e], ex[e] * invs);
    }
}

__global__ void offsets_kernel(float* __restrict__ out, int out_size) {
    __shared__ int spad[N_EXP + 1];
    int tid = threadIdx.x;
    if (tid == 0) {
        int off = 0;
        for (int e = 0; e < N_EXP; e++) {
            g_padoff[e] = off;
            off += ((g_counts[e] + 127) / 128) * 128;
        }
        g_padoff[N_EXP] = off;
        for (int e = 0; e <= N_EXP; e++) spad[e] = g_padoff[e];
        double s = 0.0;
        for (int e = 0; e < N_EXP; e++) s += (double)g_counts[e] * (double)g_psum[e];
        float aux = (float)((double)N_EXP * s / ((double)N_TOK * (double)N_TOK));
        if (out_size > N_TOK * D_MODEL) out[(size_t)N_TOK * D_MODEL] = aux;
    }
    __syncthreads();
    for (int j = tid; j < NT_DN; j += blockDim.x) {
        int row = j * 128, te = -1;
#pragma unroll
        for (int e = 0; e < N_EXP; e++)
            if (row >= spad[e] && row < spad[e + 1]) te = e;
        g_tile_dn[j] = te;
    }
}

__global__ void scatter_kernel() {
    int t = blockIdx.x * blockDim.x + threadIdx.x;
    if (t >= N_TOK) return;
#pragma unroll
    for (int k = 0; k < 2; k++) {
        int e = g_tok_idx[t * 2 + k];
        int pos = atomicAdd(&g_fill[e], 1);
        int slot = g_padoff[e] + pos;
        g_slot_token[slot] = t;
        g_tok_slot[t * 2 + k] = slot;
    }
}

// ---------------- conversions --------------------------------------------------
__global__ void conv_x_kernel(const float* __restrict__ x) {
    int i = blockIdx.x * 256 + threadIdx.x;
    g_Xh[i] = __float2half(x[i]);
}

// gate+up -> interleaved [slab][4096 n][1024 k] fp16 hi/lo
__global__ void conv_gu_kernel(const float* __restrict__ srcGs, const float* __restrict__ srcGe,
                               const float* __restrict__ srcUs, const float* __restrict__ srcUe,
                               __half* __restrict__ hiO, __half* __restrict__ loO) {
    int slab = blockIdx.z;
    const float* G = (slab == 0) ? srcGs : srcGe + (size_t)(slab - 1) * D_MODEL * D_FFN;
    const float* U = (slab == 0) ? srcUs : srcUe + (size_t)(slab - 1) * D_MODEL * D_FFN;
    size_t ob = (size_t)slab * 2 * D_FFN * D_MODEL;
    __shared__ float tg[32][33], tu[32][33];
    int tx = threadIdx.x & 31, ty = threadIdx.x >> 5;
    int k0 = blockIdx.y * 32, j0 = blockIdx.x * 32;
#pragma unroll
    for (int p = 0; p < 4; p++) {
        size_t so = (size_t)(k0 + p * 8 + ty) * D_FFN + j0 + tx;
        tg[p * 8 + ty][tx] = G[so];
        tu[p * 8 + ty][tx] = U[so];
    }
    __syncthreads();
    int nG0 = ((j0 >> 6) << 7) + (j0 & 63);
#pragma unroll
    for (int p = 0; p < 4; p++) {
        int jj = p * 8 + ty, k = k0 + tx;
        float vg = tg[tx][jj], vu = tu[tx][jj];
        __half gh = __float2half(vg);
        __half uh = __float2half(vu);
        size_t og = ob + (size_t)(nG0 + jj) * D_MODEL + k;
        size_t ou = ob + (size_t)(nG0 + 64 + jj) * D_MODEL + k;
        hiO[og] = gh; loO[og] = __float2half(vg - __half2float(gh));
        hiO[ou] = uh; loO[ou] = __float2half(vu - __half2float(uh));
    }
}

// down: transpose [R,C] fp32 -> [slab][C][R] fp16 hi/lo
__global__ void conv_w_kernel(const float* __restrict__ srcS, const float* __restrict__ srcE,
                              __half* __restrict__ hiO, __half* __restrict__ loO,
                              int R, int C) {
    int slab = blockIdx.z;
    const float* src = (slab == 0) ? srcS : srcE + (size_t)(slab - 1) * R * C;
    size_t ob = (size_t)slab * R * C;
    __shared__ float t[32][33];
    int tx = threadIdx.x & 31, ty = threadIdx.x >> 5;
    int r0 = blockIdx.y * 32, c0 = blockIdx.x * 32;
#pragma unroll
    for (int p = 0; p < 4; p++)
        t[p * 8 + ty][tx] = src[(size_t)(r0 + p * 8 + ty) * C + c0 + tx];
    __syncthreads();
#pragma unroll
    for (int p = 0; p < 4; p++) {
        int n = c0 + p * 8 + ty, k = r0 + tx;
        float v = t[tx][p * 8 + ty];
        __half h = __float2half(v);
        hiO[ob + (size_t)n * R + k] = h;
        loO[ob + (size_t)n * R + k] = __float2half(v - __half2float(h));
    }
}

// ---------------- gate+up GEMM: 128M x 128N(=64G+64U), 2-term per K sweep ------
// A single fp16, B fp16 hi/lo. One __syncthreads per K-stage.
__global__ void __launch_bounds__(256, 2) mma_gateup_kernel() {
    const int by = blockIdx.y;
    const bool sh = (by < NT_SH);
    int te = 0, r0;
    if (sh) r0 = by * 128;
    else {
        int be = by - NT_SH;
        te = g_tile_dn[be];
        if (te < 0) return;
        r0 = be * 128;
    }
    const int slab = sh ? 0 : 1 + te;
    const int n0b = blockIdx.x * 128;        // interleaved B row base
    const int h0 = blockIdx.x * 64;          // H column base
    const int tid = threadIdx.x, lane = tid & 31, wid = tid >> 5;
    const int wm = wid & 3, wn = wid >> 2;

    extern __shared__ __align__(16) char smem[];
    __shared__ int stok[128];
    const uint32_t sbase = s2u(smem);

    if (tid < 128) {
        if (sh) stok[tid] = r0 + tid;
        else { int t = g_slot_token[r0 + tid]; stok[tid] = t < 0 ? 0 : t; }
    }
    __syncthreads();

    const __half* __restrict__ Bh = g_Bgu_hi + (size_t)slab * 2 * D_FFN * D_MODEL;
    const __half* __restrict__ Bl = g_Bgu_lo + (size_t)slab * 2 * D_FFN * D_MODEL;

    auto load_stage = [&](int s) {
        const int k0 = s << 5;
        const uint32_t st = sbase + (s & 1) * STG_B;
        {
            int row = tid >> 1, ch = tid & 1;  // A: 128 rows x 2 chunks x 2 halves
#pragma unroll
            for (int half = 0; half < 2; half++) {
                uint32_t off = row * 80 + (ch * 2 + half) * 16;
                cpa16(st + off,
                      g_Xh + (size_t)stok[row] * D_MODEL + k0 + (ch * 2 + half) * 8);
            }
        }
        {
            int row = tid >> 1, ch = tid & 1;
#pragma unroll
            for (int half = 0; half < 2; half++) {
                uint32_t off = row * 80 + (ch * 2 + half) * 16;
                size_t bo = (size_t)(n0b + row) * D_MODEL + k0 + (ch * 2 + half) * 8;
                cpa16(st + TILE_B + off,     Bh + bo);
                cpa16(st + 2 * TILE_B + off, Bl + bo);
            }
        }
        cp_commit();
    };

    float acc[2][8][4];
#pragma unroll
    for (int i = 0; i < 2; i++)
#pragma unroll
        for (int j = 0; j < 8; j++)
#pragma unroll
            for (int q = 0; q < 4; q++) acc[i][j][q] = 0.f;

    load_stage(0);
    for (int s = 0; s < GU_NSTG; s++) {
        cp_wait<0>();
        __syncthreads();
        if (s + 1 < GU_NSTG) load_stage(s + 1);
        const uint32_t st = sbase + (s & 1) * STG_B;
        const int lr = lane & 15, lc = (lane >> 4) * 16;
#pragma unroll
        for (int kh = 0; kh < 2; kh++) {
            const int kb = kh * 32 + lc;
            uint32_t a[2][4];
#pragma unroll
            for (int mi = 0; mi < 2; mi++)
                ldm4(a[mi], st + (wm * 32 + mi * 16 + lr) * 80 + kb);
#pragma unroll
            for (int nj = 0; nj < 4; nj++) {
                uint32_t bh[4], bl[4];
                uint32_t ro = (wn * 64 + nj * 16 + lr) * 80 + kb;
                ldm4(bh, st + TILE_B + ro);
                ldm4(bl, st + 2 * TILE_B + ro);
#pragma unroll
                for (int mi = 0; mi < 2; mi++) {
                    mma_f16(acc[mi][nj * 2],     a[mi], bh[0], bh[2]);
                    mma_f16(acc[mi][nj * 2 + 1], a[mi], bh[1], bh[3]);
                    mma_f16(acc[mi][nj * 2],     a[mi], bl[0], bl[2]);
                    mma_f16(acc[mi][nj * 2 + 1], a[mi], bl[1], bl[3]);
                }
            }
        }
    }

    // SwiGLU epilogue: G warps (wn=0) hand accumulators to U warps (wn=1) via smem
    __syncthreads();
    float* gbuf = (float*)smem;
    if (wn == 0) {
#pragma unroll
        for (int mi = 0; mi < 2; mi++)
#pragma unroll
            for (int ni = 0; ni < 8; ni++)
#pragma unroll
                for (int hh = 0; hh < 2; hh++) {
                    int row = wm * 32 + mi * 16 + (lane >> 2) + hh * 8;
                    int col = ni * 8 + 2 * (lane & 3);
                    float2 v; v.x = acc[mi][ni][hh * 2]; v.y = acc[mi][ni][hh * 2 + 1];
                    *(float2*)(gbuf + row * 66 + col) = v;
                }
    }
    __syncthreads();
    if (wn == 1) {
        __half* __restrict__ H = sh ? g_Hs : g_He;
#pragma unroll
        for (int mi = 0; mi < 2; mi++)
#pragma unroll
            for (int ni = 0; ni < 8; ni++)
#pragma unroll
                for (int hh = 0; hh < 2; hh++) {
                    int row = wm * 32 + mi * 16 + (lane >> 2) + hh * 8;
                    int col = ni * 8 + 2 * (lane & 3);
                    float2 g2 = *(const float2*)(gbuf + row * 66 + col);
                    float u0 = acc[mi][ni][hh * 2], u1 = acc[mi][ni][hh * 2 + 1];
                    float h0v = g2.x / (1.f + expf(-g2.x)) * u0;
                    float h1v = g2.y / (1.f + expf(-g2.y)) * u1;
                    __half2 hv;
                    hv.x = __float2half(h0v);
                    hv.y = __float2half(h1v);
                    *(__half2*)(H + (size_t)(r0 + row) * D_FFN + h0 + col) = hv;
                }
    }
}

// ---------------- down GEMM: 128M x 128N, 2-term per K sweep --------------------
__global__ void __launch_bounds__(256, 2) mma_down_kernel() {
    const int by = blockIdx.y;
    const bool sh = (by < NT_SH);
    int te = 0, r0;
    if (sh) r0 = by * 128;
    else {
        int be = by - NT_SH;
        te = g_tile_dn[be];
        if (te < 0) return;
        r0 = be * 128;
    }
    const int slab = sh ? 0 : 1 + te;
    const int n0 = blockIdx.x * 128;
    const int tid = threadIdx.x, lane = tid & 31, wid = tid >> 5;
    const int wm = wid & 3, wn = wid >> 2;

    extern __shared__ __align__(16) char smem[];
    const uint32_t sbase = s2u(smem);

    const __half* __restrict__ Ah = sh ? g_Hs : g_He;
    const __half* __restrict__ Bh = g_Bd_hi + (size_t)slab * D_MODEL * D_FFN;
    const __half* __restrict__ Bl = g_Bd_lo + (size_t)slab * D_MODEL * D_FFN;

    auto load_stage = [&](int s) {
        const int k0 = s << 5;
        const uint32_t st = sbase + (s & 1) * STG_B;
        {
            int row = tid >> 1, ch = tid & 1;
#pragma unroll
            for (int half = 0; half < 2; half++) {
                uint32_t off = row * 80 + (ch * 2 + half) * 16;
                cpa16(st + off,
                      Ah + (size_t)(r0 + row) * D_FFN + k0 + (ch * 2 + half) * 8);
            }
        }
        {
            int row = tid >> 1, ch = tid & 1;
#pragma unroll
            for (int half = 0; half < 2; half++) {
                uint32_t off = row * 80 + (ch * 2 + half) * 16;
                size_t bo = (size_t)(n0 + row) * D_FFN + k0 + (ch * 2 + half) * 8;
                cpa16(st + TILE_B + off,     Bh + bo);
                cpa16(st + 2 * TILE_B + off, Bl + bo);
            }
        }
        cp_commit();
    };

    float acc[2][8][4];
#pragma unroll
    for (int i = 0; i < 2; i++)
#pragma unroll
        for (int j = 0; j < 8; j++)
#pragma unroll
            for (int q = 0; q < 4; q++) acc[i][j][q] = 0.f;

    load_stage(0);
    for (int s = 0; s < DN_NSTG; s++) {
        cp_wait<0>();
        __syncthreads();
        if (s + 1 < DN_NSTG) load_stage(s + 1);
        const uint32_t st = sbase + (s & 1) * STG_B;
        const int lr = lane & 15, lc = (lane >> 4) * 16;
#pragma unroll
        for (int kh = 0; kh < 2; kh++) {
            const int kb = kh * 32 + lc;
            uint32_t a[2][4];
#pragma unroll
            for (int mi = 0; mi < 2; mi++)
                ldm4(a[mi], st + (wm * 32 + mi * 16 + lr) * 80 + kb);
#pragma unroll
            for (int nj = 0; nj < 4; nj++) {
                uint32_t bh[4], bl[4];
                uint32_t ro = (wn * 64 + nj * 16 + lr) * 80 + kb;
                ldm4(bh, st + TILE_B + ro);
                ldm4(bl, st + 2 * TILE_B + ro);
#pragma unroll
                for (int mi = 0; mi < 2; mi++) {
                    mma_f16(acc[mi][nj * 2],     a[mi], bh[0], bh[2]);
                    mma_f16(acc[mi][nj * 2 + 1], a[mi], bh[1], bh[3]);
                    mma_f16(acc[mi][nj * 2],     a[mi], bl[0], bl[2]);
                    mma_f16(acc[mi][nj * 2 + 1], a[mi], bl[1], bl[3]);
                }
            }
        }
    }

    float* __restrict__ O = sh ? g_Os : g_Oe;
#pragma unroll
    for (int mi = 0; mi < 2; mi++)
#pragma unroll
        for (int ni = 0; ni < 8; ni++)
#pragma unroll
            for (int hh = 0; hh < 2; hh++) {
                int row = wm * 32 + mi * 16 + (lane >> 2) + hh * 8;
                int col = n0 + wn * 64 + ni * 8 + 2 * (lane & 3);
                float2 v; v.x = acc[mi][ni][hh * 2]; v.y = acc[mi][ni][hh * 2 + 1];
                *(float2*)(O + (size_t)(r0 + row) * D_MODEL + col) = v;
            }
}

// ---------------- combine: out = Os + w0*Oe[s0] + w1*Oe[s1] -----------------------
__global__ void combine_kernel(float* __restrict__ out) {
    int t = blockIdx.x;
    int tid = threadIdx.x;
    int s0 = g_tok_slot[t * 2 + 0], s1 = g_tok_slot[t * 2 + 1];
    float w0 = g_tok_w[t * 2 + 0],  w1 = g_tok_w[t * 2 + 1];
    const float4* a = (const float4*)(g_Os + (size_t)t * D_MODEL) + tid;
    const float4* b = (const float4*)(g_Oe + (size_t)s0 * D_MODEL) + tid;
    const float4* c = (const float4*)(g_Oe + (size_t)s1 * D_MODEL) + tid;
    float4 va = *a, vb = *b, vc = *c;
    float4 r;
    r.x = va.x + w0 * vb.x + w1 * vc.x;
    r.y = va.y + w0 * vb.y + w1 * vc.y;
    r.z = va.z + w0 * vb.z + w1 * vc.z;
    r.w = va.w + w0 * vb.w + w1 * vc.w;
    *((float4*)(out + (size_t)t * D_MODEL) + tid) = r;
}

// ---------------- launch ------------------------------------------------------------
extern "C" void kernel_launch(void* const* d_in, const int* in_sizes, int n_in,
                              void* d_out, int out_size) {
    const float* x         = (const float*)d_in[0];
    const float* shared_wg = (const float*)d_in[1];
    const float* shared_wu = (const float*)d_in[2];
    const float* shared_wd = (const float*)d_in[3];
    const float* exp_wg    = (const float*)d_in[4];
    const float* exp_wu    = (const float*)d_in[5];
    const float* exp_wd    = (const float*)d_in[6];
    const float* router_w  = (const float*)d_in[7];
    float* out = (float*)d_out;

    __half *bgu_hi, *bgu_lo, *bd_hi, *bd_lo;
    cudaGetSymbolAddress((void**)&bgu_hi, g_Bgu_hi);
    cudaGetSymbolAddress((void**)&bgu_lo, g_Bgu_lo);
    cudaGetSymbolAddress((void**)&bd_hi, g_Bd_hi);
    cudaGetSymbolAddress((void**)&bd_lo, g_Bd_lo);

    cudaFuncSetAttribute(mma_gateup_kernel,
                         cudaFuncAttributeMaxDynamicSharedMemorySize, MM_SMEM);
    cudaFuncSetAttribute(mma_down_kernel,
                         cudaFuncAttributeMaxDynamicSharedMemorySize, MM_SMEM);

    init_kernel<<<(MAXSLOT + 255) / 256, 256>>>();
    router_kernel<<<N_TOK / 4, 128>>>(x, router_w);
    offsets_kernel<<<1, 128>>>(out, out_size);
    scatter_kernel<<<N_TOK / 256, 256>>>();

    conv_x_kernel<<<(N_TOK * D_MODEL) / 256, 256>>>(x);
    conv_gu_kernel<<<dim3(D_FFN / 32, D_MODEL / 32, 9), 256>>>(
        shared_wg, exp_wg, shared_wu, exp_wu, bgu_hi, bgu_lo);
    conv_w_kernel<<<dim3(D_MODEL / 32, D_FFN / 32, 9), 256>>>(
        shared_wd, exp_wd, bd_hi, bd_lo, D_FFN, D_MODEL);

    mma_gateup_kernel<<<dim3(D_FFN / 64, NT_SH + NT_DN), 256, MM_SMEM>>>();
    mma_down_kernel<<<dim3(D_MODEL / 128, NT_SH + NT_DN), 256, MM_SMEM>>>();
    combine_kernel<<<N_TOK, 256>>>(out);
}

// round 11
// speedup vs baseline: 4.3083x; 1.5481x over previous
#include <cuda_runtime.h>
#include <cuda_fp16.h>
#include <math.h>
#include <stdint.h>

#define D_MODEL 1024
#define D_FFN   2048
#define N_TOK   4096
#define N_EXP   8
#define MAXSLOT 9216
#define NT_SH   (N_TOK / 128)     /* 32 shared row tiles */
#define NT_DN   (MAXSLOT / 128)   /* 72 expert row tiles */

#define TILE_B  10240             /* 128 rows * 80B (padded 64B row) */
#define STG_B   (2 * TILE_B)      /* A, B = 20480 */
#define MM_SMEM (2 * STG_B)       /* 40960, 2-stage ring */
#define GU_NSTG 32                /* K=1024 / 32 */
#define DN_NSTG 64                /* K=2048 / 32 */

// ---------------- scratch ----------------------------------------------------
__device__ __half g_Xh[(size_t)N_TOK * D_MODEL];
// gate+up interleaved: [slab][4096 n][1024 k]; n-chunk c (128 wide) = G cols
// [64c,64c+64) at +0..63, U cols [64c,64c+64) at +64..127
__device__ __half g_Bgu[(size_t)9 * 2 * D_FFN * D_MODEL];
__device__ __half g_Bd[(size_t)9 * D_MODEL * D_FFN];
__device__ __half g_Hs[(size_t)N_TOK * D_FFN];
__device__ __half g_He[(size_t)MAXSLOT * D_FFN];
__device__ float g_Os[(size_t)N_TOK * D_MODEL];
__device__ float g_Oe[(size_t)MAXSLOT * D_MODEL];
__device__ int   g_slot_token[MAXSLOT];
__device__ int   g_counts[N_EXP];
__device__ float g_psum[N_EXP];
__device__ int   g_fill[N_EXP];
__device__ int   g_padoff[N_EXP + 1];
__device__ int   g_tile_dn[NT_DN];
__device__ int   g_tok_idx[N_TOK * 2];
__device__ int   g_tok_slot[N_TOK * 2];
__device__ float g_tok_w[N_TOK * 2];

// ---------------- PTX helpers -------------------------------------------------
__device__ __forceinline__ uint32_t s2u(const void* p) {
    return (uint32_t)__cvta_generic_to_shared(p);
}
__device__ __forceinline__ void cpa16(uint32_t dst, const void* src) {
    asm volatile("cp.async.cg.shared.global [%0], [%1], 16;" :: "r"(dst), "l"(src));
}
__device__ __forceinline__ void cp_commit() {
    asm volatile("cp.async.commit_group;");
}
template <int N>
__device__ __forceinline__ void cp_wait() {
    asm volatile("cp.async.wait_group %0;" :: "n"(N));
}
__device__ __forceinline__ void ldm4(uint32_t* r, uint32_t addr) {
    asm volatile("ldmatrix.sync.aligned.m8n8.x4.shared.b16 {%0,%1,%2,%3}, [%4];"
                 : "=r"(r[0]), "=r"(r[1]), "=r"(r[2]), "=r"(r[3]) : "r"(addr));
}
__device__ __forceinline__ void mma_f16(float* c, const uint32_t* a,
                                        uint32_t b0, uint32_t b1) {
    asm volatile("mma.sync.aligned.m16n8k16.row.col.f32.f16.f16.f32 "
                 "{%0,%1,%2,%3}, {%4,%5,%6,%7}, {%8,%9}, {%0,%1,%2,%3};"
                 : "+f"(c[0]), "+f"(c[1]), "+f"(c[2]), "+f"(c[3])
                 : "r"(a[0]), "r"(a[1]), "r"(a[2]), "r"(a[3]), "r"(b0), "r"(b1));
}

// ---------------- routing kernels ---------------------------------------------
__global__ void init_kernel() {
    int i = blockIdx.x * blockDim.x + threadIdx.x;
    if (i < MAXSLOT) g_slot_token[i] = -1;
    if (i < N_EXP) { g_counts[i] = 0; g_psum[i] = 0.f; g_fill[i] = 0; }
}

__global__ void router_kernel(const float* __restrict__ x,
                              const float* __restrict__ rw) {
    int t = blockIdx.x * 4 + (threadIdx.x >> 5);
    int lane = threadIdx.x & 31;
    if (t >= N_TOK) return;
    const float* xr = x + (size_t)t * D_MODEL;
    float acc[N_EXP];
#pragma unroll
    for (int e = 0; e < N_EXP; e++) acc[e] = 0.f;
    for (int k = lane; k < D_MODEL; k += 32) {
        float xv = xr[k];
#pragma unroll
        for (int e = 0; e < N_EXP; e++) acc[e] += xv * rw[k * N_EXP + e];
    }
#pragma unroll
    for (int e = 0; e < N_EXP; e++)
#pragma unroll
        for (int o = 16; o; o >>= 1) acc[e] += __shfl_xor_sync(0xffffffffu, acc[e], o);
    if (lane == 0) {
        int i0 = 0; float v0 = acc[0];
#pragma unroll
        for (int e = 1; e < N_EXP; e++) if (acc[e] > v0) { v0 = acc[e]; i0 = e; }
        int i1 = -1; float v1 = -1e30f;
#pragma unroll
        for (int e = 0; e < N_EXP; e++) {
            if (e == i0) continue;
            if (acc[e] > v1) { v1 = acc[e]; i1 = e; }
        }
        float m2 = fmaxf(v0, v1);
        float e0 = expf(v0 - m2), e1 = expf(v1 - m2);
        float inv = 1.f / (e0 + e1);
        g_tok_idx[t * 2 + 0] = i0;  g_tok_w[t * 2 + 0] = e0 * inv;
        g_tok_idx[t * 2 + 1] = i1;  g_tok_w[t * 2 + 1] = e1 * inv;
        atomicAdd(&g_counts[i0], 1);
        atomicAdd(&g_counts[i1], 1);
        float mm = acc[0];
#pragma unroll
        for (int e = 1; e < N_EXP; e++) mm = fmaxf(mm, acc[e]);
        float s = 0.f, ex[N_EXP];
#pragma unroll
        for (int e = 0; e < N_EXP; e++) { ex[e] = expf(acc[e] - mm); s += ex[e]; }
        float invs = 1.f / s;
#pragma unroll
        for (int e = 0; e < N_EXP; e++) atomicAdd(&g_psum[e], ex[e] * invs);
    }
}

__global__ void offsets_kernel(float* __restrict__ out, int out_size) {
    __shared__ int spad[N_EXP + 1];
    int tid = threadIdx.x;
    if (tid == 0) {
        int off = 0;
        for (int e = 0; e < N_EXP; e++) {
            g_padoff[e] = off;
            off += ((g_counts[e] + 127) / 128) * 128;
        }
        g_padoff[N_EXP] = off;
        for (int e = 0; e <= N_EXP; e++) spad[e] = g_padoff[e];
        double s = 0.0;
        for (int e = 0; e < N_EXP; e++) s += (double)g_counts[e] * (double)g_psum[e];
        float aux = (float)((double)N_EXP * s / ((double)N_TOK * (double)N_TOK));
        if (out_size > N_TOK * D_MODEL) out[(size_t)N_TOK * D_MODEL] = aux;
    }
    __syncthreads();
    for (int j = tid; j < NT_DN; j += blockDim.x) {
        int row = j * 128, te = -1;
#pragma unroll
        for (int e = 0; e < N_EXP; e++)
            if (row >= spad[e] && row < spad[e + 1]) te = e;
        g_tile_dn[j] = te;
    }
}

__global__ void scatter_kernel() {
    int t = blockIdx.x * blockDim.x + threadIdx.x;
    if (t >= N_TOK) return;
#pragma unroll
    for (int k = 0; k < 2; k++) {
        int e = g_tok_idx[t * 2 + k];
        int pos = atomicAdd(&g_fill[e], 1);
        int slot = g_padoff[e] + pos;
        g_slot_token[slot] = t;
        g_tok_slot[t * 2 + k] = slot;
    }
}

// ---------------- conversions --------------------------------------------------
__global__ void conv_x_kernel(const float* __restrict__ x) {
    int i = blockIdx.x * 256 + threadIdx.x;
    g_Xh[i] = __float2half(x[i]);
}

// gate+up -> interleaved [slab][4096 n][1024 k] fp16
__global__ void conv_gu_kernel(const float* __restrict__ srcGs, const float* __restrict__ srcGe,
                               const float* __restrict__ srcUs, const float* __restrict__ srcUe,
                               __half* __restrict__ o) {
    int slab = blockIdx.z;
    const float* G = (slab == 0) ? srcGs : srcGe + (size_t)(slab - 1) * D_MODEL * D_FFN;
    const float* U = (slab == 0) ? srcUs : srcUe + (size_t)(slab - 1) * D_MODEL * D_FFN;
    size_t ob = (size_t)slab * 2 * D_FFN * D_MODEL;
    __shared__ float tg[32][33], tu[32][33];
    int tx = threadIdx.x & 31, ty = threadIdx.x >> 5;
    int k0 = blockIdx.y * 32, j0 = blockIdx.x * 32;
#pragma unroll
    for (int p = 0; p < 4; p++) {
        size_t so = (size_t)(k0 + p * 8 + ty) * D_FFN + j0 + tx;
        tg[p * 8 + ty][tx] = G[so];
        tu[p * 8 + ty][tx] = U[so];
    }
    __syncthreads();
    int nG0 = ((j0 >> 6) << 7) + (j0 & 63);
#pragma unroll
    for (int p = 0; p < 4; p++) {
        int jj = p * 8 + ty, k = k0 + tx;
        o[ob + (size_t)(nG0 + jj) * D_MODEL + k]      = __float2half(tg[tx][jj]);
        o[ob + (size_t)(nG0 + 64 + jj) * D_MODEL + k] = __float2half(tu[tx][jj]);
    }
}

// down: transpose [R,C] fp32 -> [slab][C][R] fp16
__global__ void conv_w_kernel(const float* __restrict__ srcS, const float* __restrict__ srcE,
                              __half* __restrict__ o, int R, int C) {
    int slab = blockIdx.z;
    const float* src = (slab == 0) ? srcS : srcE + (size_t)(slab - 1) * R * C;
    size_t ob = (size_t)slab * R * C;
    __shared__ float t[32][33];
    int tx = threadIdx.x & 31, ty = threadIdx.x >> 5;
    int r0 = blockIdx.y * 32, c0 = blockIdx.x * 32;
#pragma unroll
    for (int p = 0; p < 4; p++)
        t[p * 8 + ty][tx] = src[(size_t)(r0 + p * 8 + ty) * C + c0 + tx];
    __syncthreads();
#pragma unroll
    for (int p = 0; p < 4; p++) {
        int n = c0 + p * 8 + ty, k = r0 + tx;
        o[ob + (size_t)n * R + k] = __float2half(t[tx][p * 8 + ty]);
    }
}

// ---------------- gate+up GEMM: 128M x 128N(=64G+64U), single fp16 term ---------
__global__ void __launch_bounds__(256, 2) mma_gateup_kernel() {
    const int by = blockIdx.y;
    const bool sh = (by < NT_SH);
    int te = 0, r0;
    if (sh) r0 = by * 128;
    else {
        int be = by - NT_SH;
        te = g_tile_dn[be];
        if (te < 0) return;
        r0 = be * 128;
    }
    const int slab = sh ? 0 : 1 + te;
    const int n0b = blockIdx.x * 128;        // interleaved B row base
    const int h0 = blockIdx.x * 64;          // H column base
    const int tid = threadIdx.x, lane = tid & 31, wid = tid >> 5;
    const int wm = wid & 3, wn = wid >> 2;

    extern __shared__ __align__(16) char smem[];
    __shared__ int stok[128];
    const uint32_t sbase = s2u(smem);

    if (tid < 128) {
        if (sh) stok[tid] = r0 + tid;
        else { int t = g_slot_token[r0 + tid]; stok[tid] = t < 0 ? 0 : t; }
    }
    __syncthreads();

    const __half* __restrict__ B = g_Bgu + (size_t)slab * 2 * D_FFN * D_MODEL;

    auto load_stage = [&](int s) {
        const int k0 = s << 5;
        const uint32_t st = sbase + (s & 1) * STG_B;
        {
            int row = tid >> 1, ch = tid & 1;
#pragma unroll
            for (int half = 0; half < 2; half++) {
                uint32_t off = row * 80 + (ch * 2 + half) * 16;
                cpa16(st + off,
                      g_Xh + (size_t)stok[row] * D_MODEL + k0 + (ch * 2 + half) * 8);
                cpa16(st + TILE_B + off,
                      B + (size_t)(n0b + row) * D_MODEL + k0 + (ch * 2 + half) * 8);
            }
        }
        cp_commit();
    };

    float acc[2][8][4];
#pragma unroll
    for (int i = 0; i < 2; i++)
#pragma unroll
        for (int j = 0; j < 8; j++)
#pragma unroll
            for (int q = 0; q < 4; q++) acc[i][j][q] = 0.f;

    load_stage(0);
    for (int s = 0; s < GU_NSTG; s++) {
        cp_wait<0>();
        __syncthreads();
        if (s + 1 < GU_NSTG) load_stage(s + 1);
        const uint32_t st = sbase + (s & 1) * STG_B;
        const int lr = lane & 15, lc = (lane >> 4) * 16;
#pragma unroll
        for (int kh = 0; kh < 2; kh++) {
            const int kb = kh * 32 + lc;
            uint32_t a[2][4];
#pragma unroll
            for (int mi = 0; mi < 2; mi++)
                ldm4(a[mi], st + (wm * 32 + mi * 16 + lr) * 80 + kb);
#pragma unroll
            for (int nj = 0; nj < 4; nj++) {
                uint32_t bf[4];
                ldm4(bf, st + TILE_B + (wn * 64 + nj * 16 + lr) * 80 + kb);
#pragma unroll
                for (int mi = 0; mi < 2; mi++) {
                    mma_f16(acc[mi][nj * 2],     a[mi], bf[0], bf[2]);
                    mma_f16(acc[mi][nj * 2 + 1], a[mi], bf[1], bf[3]);
                }
            }
        }
    }

    // SwiGLU epilogue: G warps (wn=0) hand accumulators to U warps (wn=1) via smem
    __syncthreads();
    float* gbuf = (float*)smem;
    if (wn == 0) {
#pragma unroll
        for (int mi = 0; mi < 2; mi++)
#pragma unroll
            for (int ni = 0; ni < 8; ni++)
#pragma unroll
                for (int hh = 0; hh < 2; hh++) {
                    int row = wm * 32 + mi * 16 + (lane >> 2) + hh * 8;
                    int col = ni * 8 + 2 * (lane & 3);
                    float2 v; v.x = acc[mi][ni][hh * 2]; v.y = acc[mi][ni][hh * 2 + 1];
                    *(float2*)(gbuf + row * 66 + col) = v;
                }
    }
    __syncthreads();
    if (wn == 1) {
        __half* __restrict__ H = sh ? g_Hs : g_He;
#pragma unroll
        for (int mi = 0; mi < 2; mi++)
#pragma unroll
            for (int ni = 0; ni < 8; ni++)
#pragma unroll
                for (int hh = 0; hh < 2; hh++) {
                    int row = wm * 32 + mi * 16 + (lane >> 2) + hh * 8;
                    int col = ni * 8 + 2 * (lane & 3);
                    float2 g2 = *(const float2*)(gbuf + row * 66 + col);
                    float u0 = acc[mi][ni][hh * 2], u1 = acc[mi][ni][hh * 2 + 1];
                    float h0v = g2.x / (1.f + expf(-g2.x)) * u0;
                    float h1v = g2.y / (1.f + expf(-g2.y)) * u1;
                    __half2 hv;
                    hv.x = __float2half(h0v);
                    hv.y = __float2half(h1v);
                    *(__half2*)(H + (size_t)(r0 + row) * D_FFN + h0 + col) = hv;
                }
    }
}

// ---------------- down GEMM: 128M x 128N, single fp16 term ----------------------
__global__ void __launch_bounds__(256, 2) mma_down_kernel() {
    const int by = blockIdx.y;
    const bool sh = (by < NT_SH);
    int te = 0, r0;
    if (sh) r0 = by * 128;
    else {
        int be = by - NT_SH;
        te = g_tile_dn[be];
        if (te < 0) return;
        r0 = be * 128;
    }
    const int slab = sh ? 0 : 1 + te;
    const int n0 = blockIdx.x * 128;
    const int tid = threadIdx.x, lane = tid & 31, wid = tid >> 5;
    const int wm = wid & 3, wn = wid >> 2;

    extern __shared__ __align__(16) char smem[];
    const uint32_t sbase = s2u(smem);

    const __half* __restrict__ Ah = sh ? g_Hs : g_He;
    const __half* __restrict__ B = g_Bd + (size_t)slab * D_MODEL * D_FFN;

    auto load_stage = [&](int s) {
        const int k0 = s << 5;
        const uint32_t st = sbase + (s & 1) * STG_B;
        {
            int row = tid >> 1, ch = tid & 1;
#pragma unroll
            for (int half = 0; half < 2; half++) {
                uint32_t off = row * 80 + (ch * 2 + half) * 16;
                cpa16(st + off,
                      Ah + (size_t)(r0 + row) * D_FFN + k0 + (ch * 2 + half) * 8);
                cpa16(st + TILE_B + off,
                      B + (size_t)(n0 + row) * D_FFN + k0 + (ch * 2 + half) * 8);
            }
        }
        cp_commit();
    };

    float acc[2][8][4];
#pragma unroll
    for (int i = 0; i < 2; i++)
#pragma unroll
        for (int j = 0; j < 8; j++)
#pragma unroll
            for (int q = 0; q < 4; q++) acc[i][j][q] = 0.f;

    load_stage(0);
    for (int s = 0; s < DN_NSTG; s++) {
        cp_wait<0>();
        __syncthreads();
        if (s + 1 < DN_NSTG) load_stage(s + 1);
        const uint32_t st = sbase + (s & 1) * STG_B;
        const int lr = lane & 15, lc = (lane >> 4) * 16;
#pragma unroll
        for (int kh = 0; kh < 2; kh++) {
            const int kb = kh * 32 + lc;
            uint32_t a[2][4];
#pragma unroll
            for (int mi = 0; mi < 2; mi++)
                ldm4(a[mi], st + (wm * 32 + mi * 16 + lr) * 80 + kb);
#pragma unroll
            for (int nj = 0; nj < 4; nj++) {
                uint32_t bf[4];
                ldm4(bf, st + TILE_B + (wn * 64 + nj * 16 + lr) * 80 + kb);
#pragma unroll
                for (int mi = 0; mi < 2; mi++) {
                    mma_f16(acc[mi][nj * 2],     a[mi], bf[0], bf[2]);
                    mma_f16(acc[mi][nj * 2 + 1], a[mi], bf[1], bf[3]);
                }
            }
        }
    }

    float* __restrict__ O = sh ? g_Os : g_Oe;
#pragma unroll
    for (int mi = 0; mi < 2; mi++)
#pragma unroll
        for (int ni = 0; ni < 8; ni++)
#pragma unroll
            for (int hh = 0; hh < 2; hh++) {
                int row = wm * 32 + mi * 16 + (lane >> 2) + hh * 8;
                int col = n0 + wn * 64 + ni * 8 + 2 * (lane & 3);
                float2 v; v.x = acc[mi][ni][hh * 2]; v.y = acc[mi][ni][hh * 2 + 1];
                *(float2*)(O + (size_t)(r0 + row) * D_MODEL + col) = v;
            }
}

// ---------------- combine: out = Os + w0*Oe[s0] + w1*Oe[s1] -----------------------
__global__ void combine_kernel(float* __restrict__ out) {
    int t = blockIdx.x;
    int tid = threadIdx.x;
    int s0 = g_tok_slot[t * 2 + 0], s1 = g_tok_slot[t * 2 + 1];
    float w0 = g_tok_w[t * 2 + 0],  w1 = g_tok_w[t * 2 + 1];
    const float4* a = (const float4*)(g_Os + (size_t)t * D_MODEL) + tid;
    const float4* b = (const float4*)(g_Oe + (size_t)s0 * D_MODEL) + tid;
    const float4* c = (const float4*)(g_Oe + (size_t)s1 * D_MODEL) + tid;
    float4 va = *a, vb = *b, vc = *c;
    float4 r;
    r.x = va.x + w0 * vb.x + w1 * vc.x;
    r.y = va.y + w0 * vb.y + w1 * vc.y;
    r.z = va.z + w0 * vb.z + w1 * vc.z;
    r.w = va.w + w0 * vb.w + w1 * vc.w;
    *((float4*)(out + (size_t)t * D_MODEL) + tid) = r;
}

// ---------------- launch ------------------------------------------------------------
extern "C" void kernel_launch(void* const* d_in, const int* in_sizes, int n_in,
                              void* d_out, int out_size) {
    const float* x         = (const float*)d_in[0];
    const float* shared_wg = (const float*)d_in[1];
    const float* shared_wu = (const float*)d_in[2];
    const float* shared_wd = (const float*)d_in[3];
    const float* exp_wg    = (const float*)d_in[4];
    const float* exp_wu    = (const float*)d_in[5];
    const float* exp_wd    = (const float*)d_in[6];
    const float* router_w  = (const float*)d_in[7];
    float* out = (float*)d_out;

    __half *bgu, *bd;
    cudaGetSymbolAddress((void**)&bgu, g_Bgu);
    cudaGetSymbolAddress((void**)&bd, g_Bd);

    cudaFuncSetAttribute(mma_gateup_kernel,
                         cudaFuncAttributeMaxDynamicSharedMemorySize, MM_SMEM);
    cudaFuncSetAttribute(mma_down_kernel,
                         cudaFuncAttributeMaxDynamicSharedMemorySize, MM_SMEM);

    init_kernel<<<(MAXSLOT + 255) / 256, 256>>>();
    router_kernel<<<N_TOK / 4, 128>>>(x, router_w);
    offsets_kernel<<<1, 128>>>(out, out_size);
    scatter_kernel<<<N_TOK / 256, 256>>>();

    conv_x_kernel<<<(N_TOK * D_MODEL) / 256, 256>>>(x);
    conv_gu_kernel<<<dim3(D_FFN / 32, D_MODEL / 32, 9), 256>>>(
        shared_wg, exp_wg, shared_wu, exp_wu, bgu);
    conv_w_kernel<<<dim3(D_MODEL / 32, D_FFN / 32, 9), 256>>>(
        shared_wd, exp_wd, bd, D_FFN, D_MODEL);

    mma_gateup_kernel<<<dim3(D_FFN / 64, NT_SH + NT_DN), 256, MM_SMEM>>>();
    mma_down_kernel<<<dim3(D_MODEL / 128, NT_SH + NT_DN), 256, MM_SMEM>>>();
    combine_kernel<<<N_TOK, 256>>>(out);
}